// round 1
// baseline (speedup 1.0000x reference)
#include <cuda_runtime.h>
#include <cuda_bf16.h>
#include <cstdint>

// Problem constants
#define BATCH   2
#define SEQ     2048
#define DMODEL  2048
#define NHEADS  16
#define HDIM    128
#define MROWS   (BATCH * SEQ)     // 4096

// Scratch buffers (allocation-free rule: __device__ globals)
__device__ float g_Q[(size_t)MROWS * DMODEL];   // 32 MB
__device__ float g_K[(size_t)MROWS * HDIM];     //  2 MB
__device__ float g_V[(size_t)MROWS * HDIM];     //  2 MB
__device__ float g_A[(size_t)MROWS * DMODEL];   // 32 MB (attention out, (b,t,h,d))

// ---------------------------------------------------------------------------
// GEMM: C[M,N] = A[M,K] @ W[K,N], 128x128 tile, BK=16, 256 threads, 8x8 micro
// All dims assumed divisible (M=4096, N in {128,2048}, K=2048).
// ---------------------------------------------------------------------------
__device__ __forceinline__ void gemm_tile_128(
    const float* __restrict__ A, const float* __restrict__ W,
    float* __restrict__ C, int M, int N, int K)
{
    constexpr int BM = 128, BN = 128, BK = 16;
    __shared__ float As[BK][BM + 4];  // stored transposed: As[kk][row]
    __shared__ float Ws[BK][BN + 4];

    const int tid = threadIdx.x;
    const int tx = tid & 15;     // col group (8 cols)
    const int ty = tid >> 4;     // row group (8 rows)
    const int row0 = blockIdx.y * BM;
    const int col0 = blockIdx.x * BN;

    float acc[8][8];
#pragma unroll
    for (int i = 0; i < 8; i++)
#pragma unroll
        for (int j = 0; j < 8; j++) acc[i][j] = 0.f;

    for (int kb = 0; kb < K; kb += BK) {
        __syncthreads();
        // load A tile (128 x 16), store transposed
#pragma unroll
        for (int i = 0; i < 2; i++) {
            int idx = tid + 256 * i;          // 0..511 float4 slots
            int r   = idx >> 2;               // 0..127
            int c4  = (idx & 3) * 4;          // 0,4,8,12
            float4 v = *(const float4*)&A[(size_t)(row0 + r) * K + kb + c4];
            As[c4 + 0][r] = v.x;
            As[c4 + 1][r] = v.y;
            As[c4 + 2][r] = v.z;
            As[c4 + 3][r] = v.w;
        }
        // load W tile (16 x 128)
#pragma unroll
        for (int i = 0; i < 2; i++) {
            int idx = tid + 256 * i;          // 0..511
            int r   = idx >> 5;               // 0..15
            int c4  = (idx & 31) * 4;         // 0..124
            *(float4*)&Ws[r][c4] =
                *(const float4*)&W[(size_t)(kb + r) * N + col0 + c4];
        }
        __syncthreads();
#pragma unroll
        for (int kk = 0; kk < BK; kk++) {
            float a[8], b[8];
            *(float4*)&a[0] = *(const float4*)&As[kk][ty * 8];
            *(float4*)&a[4] = *(const float4*)&As[kk][ty * 8 + 4];
            *(float4*)&b[0] = *(const float4*)&Ws[kk][tx * 8];
            *(float4*)&b[4] = *(const float4*)&Ws[kk][tx * 8 + 4];
#pragma unroll
            for (int i = 0; i < 8; i++)
#pragma unroll
                for (int j = 0; j < 8; j++)
                    acc[i][j] = fmaf(a[i], b[j], acc[i][j]);
        }
    }
    // store
#pragma unroll
    for (int i = 0; i < 8; i++) {
        int r = row0 + ty * 8 + i;
#pragma unroll
        for (int j = 0; j < 8; j += 4) {
            float4 v = make_float4(acc[i][j], acc[i][j + 1],
                                   acc[i][j + 2], acc[i][j + 3]);
            *(float4*)&C[(size_t)r * N + col0 + tx * 8 + j] = v;
        }
    }
}

__global__ void __launch_bounds__(256)
gemm_kernel(const float* __restrict__ A, const float* __restrict__ W,
            float* __restrict__ C, int M, int N, int K)
{
    gemm_tile_128(A, W, C, M, N, K);
}

// K and V projections fused into one launch via blockIdx.z (better SM fill)
__global__ void __launch_bounds__(256)
gemm_kv_kernel(const float* __restrict__ A,
               const float* __restrict__ Wk, const float* __restrict__ Wv,
               float* __restrict__ Kb, float* __restrict__ Vb, int M, int K)
{
    const float* W = blockIdx.z ? Wv : Wk;
    float*       C = blockIdx.z ? Vb : Kb;
    gemm_tile_128(A, W, C, M, HDIM, K);
}

// ---------------------------------------------------------------------------
// Flash-style causal MQA.
// Grid: (T/64, NHEADS, BATCH). Block: 256 threads.
// Each CTA: 64 query rows of one head; streams 64-key blocks of the shared
// KV head with online softmax. O kept in registers (4 rows x 8 cols / thread).
// ---------------------------------------------------------------------------
#define BQ  64
#define BKV 64
// smem floats: Qs 64*132 + Ks 64*129 + Vs 64*132 + Ss 64*65 + 3*64
#define ATT_SMEM_FLOATS (BQ*132 + BKV*129 + BKV*132 + BQ*65 + 3*BQ)
#define ATT_SMEM_BYTES  (ATT_SMEM_FLOATS * 4)

__global__ void __launch_bounds__(256)
mqa_kernel(const float* __restrict__ Qb, const float* __restrict__ Kb,
           const float* __restrict__ Vb, float* __restrict__ Ob)
{
    extern __shared__ float sm[];
    float* Qs   = sm;                     // [BQ][132]  (scaled Q)
    float* Ks   = Qs + BQ * 132;          // [BKV][129] (K rows, odd stride)
    float* Vs   = Ks + BKV * 129;         // [BKV][132]
    float* Ss   = Vs + BKV * 132;         // [BQ][65]   (scores -> probs)
    float* mrow = Ss + BQ * 65;           // [BQ]
    float* lrow = mrow + BQ;              // [BQ]
    float* crow = lrow + BQ;              // [BQ]

    const int tid = threadIdx.x;
    const int qt = blockIdx.x, h = blockIdx.y, b = blockIdx.z;
    const int q0 = qt * BQ;
    const float scale = 0.08838834764831845f;   // 1/sqrt(128)

    // load Q tile, folding in the softmax scale
    const float* Qg = Qb + ((size_t)(b * SEQ + q0)) * DMODEL + h * HDIM;
#pragma unroll
    for (int i = 0; i < 8; i++) {
        int idx = tid + i * 256;          // 0..2047 float4 slots (64 x 32)
        int r = idx >> 5;
        int c4 = (idx & 31) * 4;
        float4 v = *(const float4*)&Qg[(size_t)r * DMODEL + c4];
        v.x *= scale; v.y *= scale; v.z *= scale; v.w *= scale;
        *(float4*)&Qs[r * 132 + c4] = v;
    }
    if (tid < BQ) { mrow[tid] = -3.0e38f; lrow[tid] = 0.f; }

    const int ty = tid >> 4;              // 0..15 -> rows ty*4..+3
    const int tx = tid & 15;              // 0..15 -> cols (S: tx+16j, O: tx*8..)

    float o[4][8];
#pragma unroll
    for (int i = 0; i < 4; i++)
#pragma unroll
        for (int j = 0; j < 8; j++) o[i][j] = 0.f;

    const int nkb = qt + 1;               // causal: key blocks 0..qt
    for (int kb = 0; kb < nkb; kb++) {
        const int k0 = kb * BKV;
        __syncthreads();   // protect Ss/Vs reuse + init visibility
        const float* Kg = Kb + ((size_t)(b * SEQ + k0)) * HDIM;
        const float* Vg = Vb + ((size_t)(b * SEQ + k0)) * HDIM;
#pragma unroll
        for (int i = 0; i < 8; i++) {
            int idx = tid + i * 256;       // 64 rows x 32 float4
            int r = idx >> 5;
            int c4 = (idx & 31) * 4;
            float4 kv = *(const float4*)&Kg[(size_t)r * HDIM + c4];
            Ks[r * 129 + c4 + 0] = kv.x;
            Ks[r * 129 + c4 + 1] = kv.y;
            Ks[r * 129 + c4 + 2] = kv.z;
            Ks[r * 129 + c4 + 3] = kv.w;
            *(float4*)&Vs[r * 132 + c4] = *(const float4*)&Vg[(size_t)r * HDIM + c4];
        }
        __syncthreads();

        // S = Qs * Ks^T. Thread: rows ty*4+i, cols tx+16j (conflict-free K reads)
        float acc[4][4];
#pragma unroll
        for (int i = 0; i < 4; i++)
#pragma unroll
            for (int j = 0; j < 4; j++) acc[i][j] = 0.f;

#pragma unroll 4
        for (int kk = 0; kk < HDIM; kk++) {
            float qv[4];
#pragma unroll
            for (int i = 0; i < 4; i++) qv[i] = Qs[(ty * 4 + i) * 132 + kk];
            float kv[4];
#pragma unroll
            for (int j = 0; j < 4; j++) kv[j] = Ks[(tx + 16 * j) * 129 + kk];
#pragma unroll
            for (int i = 0; i < 4; i++)
#pragma unroll
                for (int j = 0; j < 4; j++)
                    acc[i][j] = fmaf(qv[i], kv[j], acc[i][j]);
        }

        const bool diag = (kb == qt);
#pragma unroll
        for (int i = 0; i < 4; i++) {
            int r = ty * 4 + i;
#pragma unroll
            for (int j = 0; j < 4; j++) {
                int c = tx + 16 * j;
                float v = acc[i][j];
                if (diag && (k0 + c > q0 + r)) v = -3.0e38f;
                Ss[r * 65 + c] = v;
            }
        }
        __syncthreads();

        // online softmax: 4 threads per row (part handles 16 cols)
        {
            int r = tid >> 2, part = tid & 3;
            float mx = -3.0e38f;
#pragma unroll
            for (int j = 0; j < 16; j++)
                mx = fmaxf(mx, Ss[r * 65 + part * 16 + j]);
            mx = fmaxf(mx, __shfl_xor_sync(0xffffffffu, mx, 1));
            mx = fmaxf(mx, __shfl_xor_sync(0xffffffffu, mx, 2));
            float mold = mrow[r];
            float mnew = fmaxf(mold, mx);
            float sum = 0.f;
#pragma unroll
            for (int j = 0; j < 16; j++) {
                float p = __expf(Ss[r * 65 + part * 16 + j] - mnew);
                Ss[r * 65 + part * 16 + j] = p;
                sum += p;
            }
            sum += __shfl_xor_sync(0xffffffffu, sum, 1);
            sum += __shfl_xor_sync(0xffffffffu, sum, 2);
            if (part == 0) {
                float cf = __expf(mold - mnew);
                mrow[r] = mnew;
                lrow[r] = lrow[r] * cf + sum;
                crow[r] = cf;
            }
        }
        __syncthreads();

        // rescale O, accumulate P @ V
        float cf[4];
#pragma unroll
        for (int i = 0; i < 4; i++) cf[i] = crow[ty * 4 + i];
#pragma unroll
        for (int i = 0; i < 4; i++)
#pragma unroll
            for (int j = 0; j < 8; j++) o[i][j] *= cf[i];

#pragma unroll 4
        for (int p = 0; p < BKV; p++) {
            float4 v0 = *(const float4*)&Vs[p * 132 + tx * 8];
            float4 v1 = *(const float4*)&Vs[p * 132 + tx * 8 + 4];
            float pw[4];
#pragma unroll
            for (int i = 0; i < 4; i++) pw[i] = Ss[(ty * 4 + i) * 65 + p];
#pragma unroll
            for (int i = 0; i < 4; i++) {
                o[i][0] = fmaf(pw[i], v0.x, o[i][0]);
                o[i][1] = fmaf(pw[i], v0.y, o[i][1]);
                o[i][2] = fmaf(pw[i], v0.z, o[i][2]);
                o[i][3] = fmaf(pw[i], v0.w, o[i][3]);
                o[i][4] = fmaf(pw[i], v1.x, o[i][4]);
                o[i][5] = fmaf(pw[i], v1.y, o[i][5]);
                o[i][6] = fmaf(pw[i], v1.z, o[i][6]);
                o[i][7] = fmaf(pw[i], v1.w, o[i][7]);
            }
        }
    }

    // epilogue: normalize and write (b, t, h, d) layout
    float* Og = Ob + ((size_t)(b * SEQ + q0)) * DMODEL + h * HDIM;
#pragma unroll
    for (int i = 0; i < 4; i++) {
        int r = ty * 4 + i;
        float linv = 1.f / lrow[r];
        float4 w0 = make_float4(o[i][0] * linv, o[i][1] * linv,
                                o[i][2] * linv, o[i][3] * linv);
        float4 w1 = make_float4(o[i][4] * linv, o[i][5] * linv,
                                o[i][6] * linv, o[i][7] * linv);
        *(float4*)&Og[(size_t)r * DMODEL + tx * 8]     = w0;
        *(float4*)&Og[(size_t)r * DMODEL + tx * 8 + 4] = w1;
    }
}

// ---------------------------------------------------------------------------
extern "C" void kernel_launch(void* const* d_in, const int* in_sizes, int n_in,
                              void* d_out, int out_size)
{
    (void)in_sizes; (void)n_in; (void)out_size;
    const float* x  = (const float*)d_in[0];
    const float* Wq = (const float*)d_in[1];
    const float* Wk = (const float*)d_in[2];
    const float* Wv = (const float*)d_in[3];
    const float* Wo = (const float*)d_in[4];
    float* out = (float*)d_out;

    float *qp, *kp, *vp, *ap;
    cudaGetSymbolAddress((void**)&qp, g_Q);
    cudaGetSymbolAddress((void**)&kp, g_K);
    cudaGetSymbolAddress((void**)&vp, g_V);
    cudaGetSymbolAddress((void**)&ap, g_A);

    dim3 blk(256);

    // Q projection: (4096 x 2048) = x @ Wq
    gemm_kernel<<<dim3(DMODEL / 128, MROWS / 128), blk>>>(x, Wq, qp,
                                                          MROWS, DMODEL, DMODEL);
    // K and V projections fused (z selects weight/output)
    gemm_kv_kernel<<<dim3(1, MROWS / 128, 2), blk>>>(x, Wk, Wv, kp, vp,
                                                     MROWS, DMODEL);
    // attention
    cudaFuncSetAttribute(mqa_kernel,
                         cudaFuncAttributeMaxDynamicSharedMemorySize,
                         ATT_SMEM_BYTES);
    mqa_kernel<<<dim3(SEQ / BQ, NHEADS, BATCH), blk, ATT_SMEM_BYTES>>>(qp, kp, vp, ap);

    // output projection
    gemm_kernel<<<dim3(DMODEL / 128, MROWS / 128), blk>>>(ap, Wo, out,
                                                          MROWS, DMODEL, DMODEL);
}

// round 3
// speedup vs baseline: 1.5995x; 1.5995x over previous
#include <cuda_runtime.h>
#include <cuda_bf16.h>
#include <cstdint>

// Problem constants
#define BATCH   2
#define SEQ     2048
#define DMODEL  2048
#define NHEADS  16
#define HDIM    128
#define MROWS   (BATCH * SEQ)     // 4096

// Scratch buffers (allocation-free rule: __device__ globals) — 68 MB total
__device__ float g_Q[(size_t)MROWS * DMODEL];    // 32 MB
__device__ float g_K[(size_t)MROWS * HDIM];      //  2 MB
__device__ float g_V[(size_t)MROWS * HDIM];      //  2 MB
__device__ float g_A[(size_t)MROWS * DMODEL];    // 32 MB (attention out)

// ---------------------------------------------------------------------------
// tf32 round-to-nearest helper (returns raw tf32 bit pattern for mma)
// ---------------------------------------------------------------------------
__device__ __forceinline__ uint32_t tf32u(float x) {
    uint32_t u;
    asm("cvt.rna.tf32.f32 %0, %1;" : "=r"(u) : "f"(x));
    return u;
}

// ---------------------------------------------------------------------------
// tf32 tensor-core GEMM: C[M,N] = A[M,K] @ W[K,N]
// 128x128x32 tile, 256 threads (8 warps, 64x32 warp tiles), mma.m16n8k8.tf32,
// 3-stage cp.async pipeline. Raw fp32 in gmem/smem; RN tf32 rounding applied
// in registers at fragment-load time (both operands).
// Smem strides 36/136 give conflict-free fragment loads.
// ---------------------------------------------------------------------------
#define GS 3
#define AS_STRIDE 36
#define BS_STRIDE 136
#define AS_FLOATS (128 * AS_STRIDE)   // 4608
#define BS_FLOATS (32 * BS_STRIDE)    // 4352
#define GEMM_SMEM_BYTES ((GS * (AS_FLOATS + BS_FLOATS)) * 4)  // 107520

__device__ __forceinline__ unsigned smem_u32(const void* p) {
    return (unsigned)__cvta_generic_to_shared(p);
}
__device__ __forceinline__ void cp_async16(unsigned dst, const void* src) {
    asm volatile("cp.async.cg.shared.global [%0], [%1], 16;\n"
                 :: "r"(dst), "l"(src));
}

__device__ __forceinline__ void gemm_tf32_body(
    const float* __restrict__ A, const float* __restrict__ W,
    float* __restrict__ C, int M, int N, int K,
    int bx, int by)
{
    extern __shared__ float sm[];
    float* As = sm;                      // [GS][128][36]
    float* Bs = sm + GS * AS_FLOATS;     // [GS][32][136]

    const int tid  = threadIdx.x;
    const int warp = tid >> 5, lane = tid & 31;
    const int g    = lane >> 2, tig = lane & 3;
    const int wm   = warp >> 2, wn = warp & 3;
    const int row0 = by * 128, col0 = bx * 128;

    float acc[4][4][4];
#pragma unroll
    for (int i = 0; i < 4; i++)
#pragma unroll
        for (int j = 0; j < 4; j++)
#pragma unroll
            for (int r = 0; r < 4; r++) acc[i][j][r] = 0.f;

    const int nk = K / 32;

    auto load_stage = [&](int kb, int s) {
        float* as = As + s * AS_FLOATS;
        float* bs = Bs + s * BS_FLOATS;
#pragma unroll
        for (int i = 0; i < 4; i++) {
            int idx = tid + 256 * i;        // 1024 float4: 128 rows x 8
            int r = idx >> 3, c4 = (idx & 7) * 4;
            cp_async16(smem_u32(&as[r * AS_STRIDE + c4]),
                       &A[(size_t)(row0 + r) * K + kb * 32 + c4]);
        }
#pragma unroll
        for (int i = 0; i < 4; i++) {
            int idx = tid + 256 * i;        // 1024 float4: 32 rows x 32
            int r = idx >> 5, c4 = (idx & 31) * 4;
            cp_async16(smem_u32(&bs[r * BS_STRIDE + c4]),
                       &W[(size_t)(kb * 32 + r) * N + col0 + c4]);
        }
        asm volatile("cp.async.commit_group;\n");
    };

#pragma unroll
    for (int s = 0; s < GS - 1; s++) load_stage(s, s);

    for (int kb = 0; kb < nk; kb++) {
        asm volatile("cp.async.wait_group %0;\n" :: "n"(GS - 2));
        __syncthreads();
        if (kb + GS - 1 < nk) load_stage(kb + GS - 1, (kb + GS - 1) % GS);

        const float* as = As + (kb % GS) * AS_FLOATS;
        const float* bs = Bs + (kb % GS) * BS_FLOATS;

#pragma unroll
        for (int ks = 0; ks < 4; ks++) {
            const int kk = ks * 8;
            uint32_t af[4][4], bf[4][2];
#pragma unroll
            for (int i = 0; i < 4; i++) {
                int r = wm * 64 + i * 16 + g;
                af[i][0] = tf32u(as[r * AS_STRIDE + kk + tig]);
                af[i][1] = tf32u(as[(r + 8) * AS_STRIDE + kk + tig]);
                af[i][2] = tf32u(as[r * AS_STRIDE + kk + tig + 4]);
                af[i][3] = tf32u(as[(r + 8) * AS_STRIDE + kk + tig + 4]);
            }
#pragma unroll
            for (int j = 0; j < 4; j++) {
                int c = wn * 32 + j * 8 + g;
                bf[j][0] = tf32u(bs[(kk + tig) * BS_STRIDE + c]);
                bf[j][1] = tf32u(bs[(kk + tig + 4) * BS_STRIDE + c]);
            }
#pragma unroll
            for (int i = 0; i < 4; i++)
#pragma unroll
                for (int j = 0; j < 4; j++) {
                    asm volatile(
                        "mma.sync.aligned.m16n8k8.row.col.f32.tf32.tf32.f32 "
                        "{%0,%1,%2,%3}, {%4,%5,%6,%7}, {%8,%9}, {%0,%1,%2,%3};\n"
                        : "+f"(acc[i][j][0]), "+f"(acc[i][j][1]),
                          "+f"(acc[i][j][2]), "+f"(acc[i][j][3])
                        : "r"(af[i][0]), "r"(af[i][1]), "r"(af[i][2]), "r"(af[i][3]),
                          "r"(bf[j][0]), "r"(bf[j][1]));
                }
        }
    }

    // epilogue
#pragma unroll
    for (int i = 0; i < 4; i++) {
        int r = row0 + wm * 64 + i * 16 + g;
#pragma unroll
        for (int j = 0; j < 4; j++) {
            int c = col0 + wn * 32 + j * 8 + 2 * tig;
            *(float2*)&C[(size_t)r * N + c] =
                make_float2(acc[i][j][0], acc[i][j][1]);
            *(float2*)&C[(size_t)(r + 8) * N + c] =
                make_float2(acc[i][j][2], acc[i][j][3]);
        }
    }
}

__global__ void __launch_bounds__(256)
gemm_tf32_kernel(const float* __restrict__ A, const float* __restrict__ W,
                 float* __restrict__ C, int M, int N, int K)
{
    gemm_tf32_body(A, W, C, M, N, K, blockIdx.x, blockIdx.y);
}

// K and V projections fused into one launch via blockIdx.z
__global__ void __launch_bounds__(256)
gemm_kv_tf32_kernel(const float* __restrict__ A,
                    const float* __restrict__ Wk, const float* __restrict__ Wv,
                    float* __restrict__ Kb, float* __restrict__ Vb, int M, int K)
{
    const float* W = blockIdx.z ? Wv : Wk;
    float*       C = blockIdx.z ? Vb : Kb;
    gemm_tf32_body(A, W, C, M, HDIM, K, 0, blockIdx.y);
}

// ---------------------------------------------------------------------------
// Flash-style causal MQA (fp32 FFMA, same as round-1 passing version).
// Grid: (T/64, NHEADS, BATCH). Block: 256 threads.
// ---------------------------------------------------------------------------
#define BQ  64
#define BKV 64
#define ATT_SMEM_FLOATS (BQ*132 + BKV*129 + BKV*132 + BQ*65 + 3*BQ)
#define ATT_SMEM_BYTES  (ATT_SMEM_FLOATS * 4)

__global__ void __launch_bounds__(256)
mqa_kernel(const float* __restrict__ Qb, const float* __restrict__ Kb,
           const float* __restrict__ Vb, float* __restrict__ Ob)
{
    extern __shared__ float sm[];
    float* Qs   = sm;                     // [BQ][132]  (scaled Q)
    float* Ks   = Qs + BQ * 132;          // [BKV][129]
    float* Vs   = Ks + BKV * 129;         // [BKV][132]
    float* Ss   = Vs + BKV * 132;         // [BQ][65]
    float* mrow = Ss + BQ * 65;
    float* lrow = mrow + BQ;
    float* crow = lrow + BQ;

    const int tid = threadIdx.x;
    const int qt = blockIdx.x, h = blockIdx.y, b = blockIdx.z;
    const int q0 = qt * BQ;
    const float scale = 0.08838834764831845f;   // 1/sqrt(128)

    const float* Qg = Qb + ((size_t)(b * SEQ + q0)) * DMODEL + h * HDIM;
#pragma unroll
    for (int i = 0; i < 8; i++) {
        int idx = tid + i * 256;
        int r = idx >> 5;
        int c4 = (idx & 31) * 4;
        float4 v = *(const float4*)&Qg[(size_t)r * DMODEL + c4];
        v.x *= scale; v.y *= scale; v.z *= scale; v.w *= scale;
        *(float4*)&Qs[r * 132 + c4] = v;
    }
    if (tid < BQ) { mrow[tid] = -3.0e38f; lrow[tid] = 0.f; }

    const int ty = tid >> 4;
    const int tx = tid & 15;

    float o[4][8];
#pragma unroll
    for (int i = 0; i < 4; i++)
#pragma unroll
        for (int j = 0; j < 8; j++) o[i][j] = 0.f;

    const int nkb = qt + 1;
    for (int kb = 0; kb < nkb; kb++) {
        const int k0 = kb * BKV;
        __syncthreads();
        const float* Kg = Kb + ((size_t)(b * SEQ + k0)) * HDIM;
        const float* Vg = Vb + ((size_t)(b * SEQ + k0)) * HDIM;
#pragma unroll
        for (int i = 0; i < 8; i++) {
            int idx = tid + i * 256;
            int r = idx >> 5;
            int c4 = (idx & 31) * 4;
            float4 kv = *(const float4*)&Kg[(size_t)r * HDIM + c4];
            Ks[r * 129 + c4 + 0] = kv.x;
            Ks[r * 129 + c4 + 1] = kv.y;
            Ks[r * 129 + c4 + 2] = kv.z;
            Ks[r * 129 + c4 + 3] = kv.w;
            *(float4*)&Vs[r * 132 + c4] = *(const float4*)&Vg[(size_t)r * HDIM + c4];
        }
        __syncthreads();

        float acc[4][4];
#pragma unroll
        for (int i = 0; i < 4; i++)
#pragma unroll
            for (int j = 0; j < 4; j++) acc[i][j] = 0.f;

#pragma unroll 4
        for (int kk = 0; kk < HDIM; kk++) {
            float qv[4];
#pragma unroll
            for (int i = 0; i < 4; i++) qv[i] = Qs[(ty * 4 + i) * 132 + kk];
            float kv[4];
#pragma unroll
            for (int j = 0; j < 4; j++) kv[j] = Ks[(tx + 16 * j) * 129 + kk];
#pragma unroll
            for (int i = 0; i < 4; i++)
#pragma unroll
                for (int j = 0; j < 4; j++)
                    acc[i][j] = fmaf(qv[i], kv[j], acc[i][j]);
        }

        const bool diag = (kb == qt);
#pragma unroll
        for (int i = 0; i < 4; i++) {
            int r = ty * 4 + i;
#pragma unroll
            for (int j = 0; j < 4; j++) {
                int c = tx + 16 * j;
                float v = acc[i][j];
                if (diag && (k0 + c > q0 + r)) v = -3.0e38f;
                Ss[r * 65 + c] = v;
            }
        }
        __syncthreads();

        {
            int r = tid >> 2, part = tid & 3;
            float mx = -3.0e38f;
#pragma unroll
            for (int j = 0; j < 16; j++)
                mx = fmaxf(mx, Ss[r * 65 + part * 16 + j]);
            mx = fmaxf(mx, __shfl_xor_sync(0xffffffffu, mx, 1));
            mx = fmaxf(mx, __shfl_xor_sync(0xffffffffu, mx, 2));
            float mold = mrow[r];
            float mnew = fmaxf(mold, mx);
            float sum = 0.f;
#pragma unroll
            for (int j = 0; j < 16; j++) {
                float p = __expf(Ss[r * 65 + part * 16 + j] - mnew);
                Ss[r * 65 + part * 16 + j] = p;
                sum += p;
            }
            sum += __shfl_xor_sync(0xffffffffu, sum, 1);
            sum += __shfl_xor_sync(0xffffffffu, sum, 2);
            if (part == 0) {
                float cf = __expf(mold - mnew);
                mrow[r] = mnew;
                lrow[r] = lrow[r] * cf + sum;
                crow[r] = cf;
            }
        }
        __syncthreads();

        float cf[4];
#pragma unroll
        for (int i = 0; i < 4; i++) cf[i] = crow[ty * 4 + i];
#pragma unroll
        for (int i = 0; i < 4; i++)
#pragma unroll
            for (int j = 0; j < 8; j++) o[i][j] *= cf[i];

#pragma unroll 4
        for (int p = 0; p < BKV; p++) {
            float4 v0 = *(const float4*)&Vs[p * 132 + tx * 8];
            float4 v1 = *(const float4*)&Vs[p * 132 + tx * 8 + 4];
            float pw[4];
#pragma unroll
            for (int i = 0; i < 4; i++) pw[i] = Ss[(ty * 4 + i) * 65 + p];
#pragma unroll
            for (int i = 0; i < 4; i++) {
                o[i][0] = fmaf(pw[i], v0.x, o[i][0]);
                o[i][1] = fmaf(pw[i], v0.y, o[i][1]);
                o[i][2] = fmaf(pw[i], v0.z, o[i][2]);
                o[i][3] = fmaf(pw[i], v0.w, o[i][3]);
                o[i][4] = fmaf(pw[i], v1.x, o[i][4]);
                o[i][5] = fmaf(pw[i], v1.y, o[i][5]);
                o[i][6] = fmaf(pw[i], v1.z, o[i][6]);
                o[i][7] = fmaf(pw[i], v1.w, o[i][7]);
            }
        }
    }

    // epilogue: normalize and write (b, t, h, d) layout
    float* Og = Ob + ((size_t)(b * SEQ + q0)) * DMODEL + h * HDIM;
#pragma unroll
    for (int i = 0; i < 4; i++) {
        int r = ty * 4 + i;
        float linv = 1.f / lrow[r];
        float4 w0 = make_float4(o[i][0] * linv, o[i][1] * linv,
                                o[i][2] * linv, o[i][3] * linv);
        float4 w1 = make_float4(o[i][4] * linv, o[i][5] * linv,
                                o[i][6] * linv, o[i][7] * linv);
        *(float4*)&Og[(size_t)r * DMODEL + tx * 8]     = w0;
        *(float4*)&Og[(size_t)r * DMODEL + tx * 8 + 4] = w1;
    }
}

// ---------------------------------------------------------------------------
extern "C" void kernel_launch(void* const* d_in, const int* in_sizes, int n_in,
                              void* d_out, int out_size)
{
    (void)in_sizes; (void)n_in; (void)out_size;
    const float* x  = (const float*)d_in[0];
    const float* Wq = (const float*)d_in[1];
    const float* Wk = (const float*)d_in[2];
    const float* Wv = (const float*)d_in[3];
    const float* Wo = (const float*)d_in[4];
    float* out = (float*)d_out;

    float *qp, *kp, *vp, *ap;
    cudaGetSymbolAddress((void**)&qp, g_Q);
    cudaGetSymbolAddress((void**)&kp, g_K);
    cudaGetSymbolAddress((void**)&vp, g_V);
    cudaGetSymbolAddress((void**)&ap, g_A);

    dim3 blk(256);

    cudaFuncSetAttribute(gemm_tf32_kernel,
                         cudaFuncAttributeMaxDynamicSharedMemorySize,
                         GEMM_SMEM_BYTES);
    cudaFuncSetAttribute(gemm_kv_tf32_kernel,
                         cudaFuncAttributeMaxDynamicSharedMemorySize,
                         GEMM_SMEM_BYTES);
    cudaFuncSetAttribute(mqa_kernel,
                         cudaFuncAttributeMaxDynamicSharedMemorySize,
                         ATT_SMEM_BYTES);

    // Q projection: (4096 x 2048) = x @ Wq
    gemm_tf32_kernel<<<dim3(DMODEL / 128, MROWS / 128), blk, GEMM_SMEM_BYTES>>>(
        x, Wq, qp, MROWS, DMODEL, DMODEL);
    // K and V projections fused (z selects weight/output)
    gemm_kv_tf32_kernel<<<dim3(1, MROWS / 128, 2), blk, GEMM_SMEM_BYTES>>>(
        x, Wk, Wv, kp, vp, MROWS, DMODEL);
    // attention (fp32 FFMA)
    mqa_kernel<<<dim3(SEQ / BQ, NHEADS, BATCH), blk, ATT_SMEM_BYTES>>>(qp, kp, vp, ap);
    // output projection
    gemm_tf32_kernel<<<dim3(DMODEL / 128, MROWS / 128), blk, GEMM_SMEM_BYTES>>>(
        ap, Wo, out, MROWS, DMODEL, DMODEL);
}

// round 4
// speedup vs baseline: 3.4893x; 2.1815x over previous
#include <cuda_runtime.h>
#include <cuda_bf16.h>
#include <cstdint>

// Problem constants
#define BATCH   2
#define SEQ     2048
#define DMODEL  2048
#define NHEADS  16
#define HDIM    128
#define MROWS   (BATCH * SEQ)     // 4096

// Scratch buffers (allocation-free rule: __device__ globals) — 68 MB total
__device__ float g_Q[(size_t)MROWS * DMODEL];    // 32 MB
__device__ float g_K[(size_t)MROWS * HDIM];      //  2 MB
__device__ float g_V[(size_t)MROWS * HDIM];      //  2 MB
__device__ float g_A[(size_t)MROWS * DMODEL];    // 32 MB (attention out)

// ---------------------------------------------------------------------------
// tf32 round-to-nearest helpers
// ---------------------------------------------------------------------------
__device__ __forceinline__ uint32_t tf32u(float x) {
    uint32_t u;
    asm("cvt.rna.tf32.f32 %0, %1;" : "=r"(u) : "f"(x));
    return u;
}
__device__ __forceinline__ float tf32f(float x) {
    return __uint_as_float(tf32u(x));
}

__device__ __forceinline__ unsigned smem_u32(const void* p) {
    return (unsigned)__cvta_generic_to_shared(p);
}
__device__ __forceinline__ void cp_async16(unsigned dst, const void* src) {
    asm volatile("cp.async.cg.shared.global [%0], [%1], 16;\n"
                 :: "r"(dst), "l"(src));
}
__device__ __forceinline__ void mma_tf32(float c[4], const uint32_t a[4],
                                         uint32_t b0, uint32_t b1) {
    asm volatile(
        "mma.sync.aligned.m16n8k8.row.col.f32.tf32.tf32.f32 "
        "{%0,%1,%2,%3}, {%4,%5,%6,%7}, {%8,%9}, {%0,%1,%2,%3};\n"
        : "+f"(c[0]), "+f"(c[1]), "+f"(c[2]), "+f"(c[3])
        : "r"(a[0]), "r"(a[1]), "r"(a[2]), "r"(a[3]), "r"(b0), "r"(b1));
}

// ---------------------------------------------------------------------------
// tf32 tensor-core GEMM: C[M,N] = A[M,K] @ W[K,N]
// 128x128x32 tile, 256 threads, mma.m16n8k8.tf32, 3-stage cp.async pipeline.
// __launch_bounds__(256,2): cap regs at 128 -> 2 CTAs/SM (round-3 occ fix).
// ---------------------------------------------------------------------------
#define GS 3
#define AS_STRIDE 36
#define BS_STRIDE 136
#define AS_FLOATS (128 * AS_STRIDE)   // 4608
#define BS_FLOATS (32 * BS_STRIDE)    // 4352
#define GEMM_SMEM_BYTES ((GS * (AS_FLOATS + BS_FLOATS)) * 4)  // 107520

__device__ __forceinline__ void gemm_tf32_body(
    const float* __restrict__ A, const float* __restrict__ W,
    float* __restrict__ C, int M, int N, int K,
    int bx, int by)
{
    extern __shared__ float sm[];
    float* As = sm;                      // [GS][128][36]
    float* Bs = sm + GS * AS_FLOATS;     // [GS][32][136]

    const int tid  = threadIdx.x;
    const int warp = tid >> 5, lane = tid & 31;
    const int g    = lane >> 2, tig = lane & 3;
    const int wm   = warp >> 2, wn = warp & 3;
    const int row0 = by * 128, col0 = bx * 128;

    float acc[4][4][4];
#pragma unroll
    for (int i = 0; i < 4; i++)
#pragma unroll
        for (int j = 0; j < 4; j++)
#pragma unroll
            for (int r = 0; r < 4; r++) acc[i][j][r] = 0.f;

    const int nk = K / 32;

    auto load_stage = [&](int kb, int s) {
        float* as = As + s * AS_FLOATS;
        float* bs = Bs + s * BS_FLOATS;
#pragma unroll
        for (int i = 0; i < 4; i++) {
            int idx = tid + 256 * i;
            int r = idx >> 3, c4 = (idx & 7) * 4;
            cp_async16(smem_u32(&as[r * AS_STRIDE + c4]),
                       &A[(size_t)(row0 + r) * K + kb * 32 + c4]);
        }
#pragma unroll
        for (int i = 0; i < 4; i++) {
            int idx = tid + 256 * i;
            int r = idx >> 5, c4 = (idx & 31) * 4;
            cp_async16(smem_u32(&bs[r * BS_STRIDE + c4]),
                       &W[(size_t)(kb * 32 + r) * N + col0 + c4]);
        }
        asm volatile("cp.async.commit_group;\n");
    };

#pragma unroll
    for (int s = 0; s < GS - 1; s++) load_stage(s, s);

    for (int kb = 0; kb < nk; kb++) {
        asm volatile("cp.async.wait_group %0;\n" :: "n"(GS - 2));
        __syncthreads();
        if (kb + GS - 1 < nk) load_stage(kb + GS - 1, (kb + GS - 1) % GS);

        const float* as = As + (kb % GS) * AS_FLOATS;
        const float* bs = Bs + (kb % GS) * BS_FLOATS;

#pragma unroll
        for (int ks = 0; ks < 4; ks++) {
            const int kk = ks * 8;
            uint32_t af[4][4], bf[4][2];
#pragma unroll
            for (int i = 0; i < 4; i++) {
                int r = wm * 64 + i * 16 + g;
                af[i][0] = tf32u(as[r * AS_STRIDE + kk + tig]);
                af[i][1] = tf32u(as[(r + 8) * AS_STRIDE + kk + tig]);
                af[i][2] = tf32u(as[r * AS_STRIDE + kk + tig + 4]);
                af[i][3] = tf32u(as[(r + 8) * AS_STRIDE + kk + tig + 4]);
            }
#pragma unroll
            for (int j = 0; j < 4; j++) {
                int c = wn * 32 + j * 8 + g;
                bf[j][0] = tf32u(bs[(kk + tig) * BS_STRIDE + c]);
                bf[j][1] = tf32u(bs[(kk + tig + 4) * BS_STRIDE + c]);
            }
#pragma unroll
            for (int i = 0; i < 4; i++)
#pragma unroll
                for (int j = 0; j < 4; j++)
                    mma_tf32(acc[i][j], af[i], bf[j][0], bf[j][1]);
        }
    }

#pragma unroll
    for (int i = 0; i < 4; i++) {
        int r = row0 + wm * 64 + i * 16 + g;
#pragma unroll
        for (int j = 0; j < 4; j++) {
            int c = col0 + wn * 32 + j * 8 + 2 * tig;
            *(float2*)&C[(size_t)r * N + c] =
                make_float2(acc[i][j][0], acc[i][j][1]);
            *(float2*)&C[(size_t)(r + 8) * N + c] =
                make_float2(acc[i][j][2], acc[i][j][3]);
        }
    }
}

__global__ void __launch_bounds__(256, 2)
gemm_tf32_kernel(const float* __restrict__ A, const float* __restrict__ W,
                 float* __restrict__ C, int M, int N, int K)
{
    gemm_tf32_body(A, W, C, M, N, K, blockIdx.x, blockIdx.y);
}

__global__ void __launch_bounds__(256, 2)
gemm_kv_tf32_kernel(const float* __restrict__ A,
                    const float* __restrict__ Wk, const float* __restrict__ Wv,
                    float* __restrict__ Kb, float* __restrict__ Vb, int M, int K)
{
    const float* W = blockIdx.z ? Wv : Wk;
    float*       C = blockIdx.z ? Vb : Kb;
    gemm_tf32_body(A, W, C, M, HDIM, K, 0, blockIdx.y);
}

// ---------------------------------------------------------------------------
// Tensor-core flash MQA (tf32 mma for QK^T and PV).
// BQ=128 queries/CTA, BKV=64 keys/iter, 256 threads (8 warps).
// Q pre-scaled + tf32-RN-rounded, held in registers (A fragments).
// K/V double-buffered via cp.async, fed raw fp32 to mma (HW RZ truncation).
// P tf32-RN-rounded in softmax; l accumulates the rounded p.
// Grid: (16, NHEADS, BATCH), blockIdx.x reversed so heavy CTAs go first.
// ---------------------------------------------------------------------------
#define BQ   128
#define BKV  64
#define KS_STRIDE 132   // 4 mod 32: QK B-frag banks = 4g+tig (conflict-free)
#define VS_STRIDE 136   // 8 mod 32: PV B-frag banks = 8*tig+g (conflict-free)
#define SS_STRIDE 68    // 4 mod 32: PV A-frag banks = 4g+tig (conflict-free)
#define KS_FLOATS (BKV * KS_STRIDE)   // 8448
#define VS_FLOATS (BKV * VS_STRIDE)   // 8704
#define SS_FLOATS (BQ * SS_STRIDE)    // 8704
// 2*KS + 2*VS + SS + 3*BQ floats
#define ATT_SMEM_FLOATS (2*KS_FLOATS + 2*VS_FLOATS + SS_FLOATS + 3*BQ)
#define ATT_SMEM_BYTES  (ATT_SMEM_FLOATS * 4)   // 173,568 B

__global__ void __launch_bounds__(256)
mqa_kernel(const float* __restrict__ Qb, const float* __restrict__ Kb,
           const float* __restrict__ Vb, float* __restrict__ Ob)
{
    extern __shared__ float sm[];
    float* KsBuf = sm;                            // [2][64][132]
    float* VsBuf = KsBuf + 2 * KS_FLOATS;         // [2][64][136]
    float* Ss    = VsBuf + 2 * VS_FLOATS;         // [128][68]
    float* mrow  = Ss + SS_FLOATS;                // [128]
    float* lrow  = mrow + BQ;
    float* crow  = lrow + BQ;

    const int tid  = threadIdx.x;
    const int warp = tid >> 5, lane = tid & 31;
    const int g    = lane >> 2, tig = lane & 3;
    const int wm   = warp;                        // 8 warps x 16 rows
    const int qt   = gridDim.x - 1 - blockIdx.x;  // heavy tiles first
    const int h    = blockIdx.y, b = blockIdx.z;
    const int q0   = qt * BQ;
    const float scale = 0.08838834764831845f;     // 1/sqrt(128)

    // ---- Q fragments in registers (pre-scaled, tf32 RN) ----
    uint32_t qreg[16][4];
    {
        const float* Qg = Qb + ((size_t)(b * SEQ + q0 + wm * 16)) * DMODEL
                             + h * HDIM;
#pragma unroll
        for (int ks = 0; ks < 16; ks++) {
            qreg[ks][0] = tf32u(scale * Qg[(size_t)g * DMODEL + ks * 8 + tig]);
            qreg[ks][1] = tf32u(scale * Qg[(size_t)(g + 8) * DMODEL + ks * 8 + tig]);
            qreg[ks][2] = tf32u(scale * Qg[(size_t)g * DMODEL + ks * 8 + tig + 4]);
            qreg[ks][3] = tf32u(scale * Qg[(size_t)(g + 8) * DMODEL + ks * 8 + tig + 4]);
        }
    }
    if (tid < BQ) { mrow[tid] = -3.0e38f; lrow[tid] = 0.f; }

    float o[16][4];
#pragma unroll
    for (int nt = 0; nt < 16; nt++)
#pragma unroll
        for (int r = 0; r < 4; r++) o[nt][r] = 0.f;

    const int nkb = 2 * qt + 2;     // causal: key blocks 0 .. 2*qt+1

    auto load_kv = [&](int kb) {
        const int buf = kb & 1;
        const float* Kg = Kb + ((size_t)(b * SEQ + kb * BKV)) * HDIM;
        const float* Vg = Vb + ((size_t)(b * SEQ + kb * BKV)) * HDIM;
        float* ks = KsBuf + buf * KS_FLOATS;
        float* vs = VsBuf + buf * VS_FLOATS;
#pragma unroll
        for (int i = 0; i < 8; i++) {
            int idx = tid + 256 * i;      // 2048 float4 = 64 rows x 32
            int r = idx >> 5, c4 = (idx & 31) * 4;
            cp_async16(smem_u32(&ks[r * KS_STRIDE + c4]),
                       &Kg[(size_t)r * HDIM + c4]);
            cp_async16(smem_u32(&vs[r * VS_STRIDE + c4]),
                       &Vg[(size_t)r * HDIM + c4]);
        }
        asm volatile("cp.async.commit_group;\n");
    };

    load_kv(0);

    for (int kb = 0; kb < nkb; kb++) {
        const int k0 = kb * BKV;
        asm volatile("cp.async.wait_group 0;\n");
        __syncthreads();
        if (kb + 1 < nkb) load_kv(kb + 1);

        const float* ks = KsBuf + (kb & 1) * KS_FLOATS;
        const float* vs = VsBuf + (kb & 1) * VS_FLOATS;

        // ---- S = Q K^T : warp = 16 rows x 64 cols (8 n-tiles) ----
        float sacc[8][4];
#pragma unroll
        for (int j = 0; j < 8; j++)
#pragma unroll
            for (int r = 0; r < 4; r++) sacc[j][r] = 0.f;

#pragma unroll
        for (int ks4 = 0; ks4 < 16; ks4++) {
            const int kk = ks4 * 8;
            uint32_t bf[8][2];
#pragma unroll
            for (int j = 0; j < 8; j++) {
                bf[j][0] = __float_as_uint(ks[(j * 8 + g) * KS_STRIDE + kk + tig]);
                bf[j][1] = __float_as_uint(ks[(j * 8 + g) * KS_STRIDE + kk + tig + 4]);
            }
#pragma unroll
            for (int j = 0; j < 8; j++)
                mma_tf32(sacc[j], qreg[ks4], bf[j][0], bf[j][1]);
        }

        // ---- mask (last two blocks touch diagonal) + store S ----
        const bool needs_mask = (k0 + BKV - 1 > q0);
        const int rg0 = q0 + wm * 16 + g, rg1 = rg0 + 8;
        const int rs0 = wm * 16 + g;
#pragma unroll
        for (int j = 0; j < 8; j++) {
            int cg = k0 + j * 8 + 2 * tig;
            float v00 = sacc[j][0], v01 = sacc[j][1];
            float v10 = sacc[j][2], v11 = sacc[j][3];
            if (needs_mask) {
                if (cg     > rg0) v00 = -3.0e38f;
                if (cg + 1 > rg0) v01 = -3.0e38f;
                if (cg     > rg1) v10 = -3.0e38f;
                if (cg + 1 > rg1) v11 = -3.0e38f;
            }
            *(float2*)&Ss[rs0 * SS_STRIDE + j * 8 + 2 * tig] =
                make_float2(v00, v01);
            *(float2*)&Ss[(rs0 + 8) * SS_STRIDE + j * 8 + 2 * tig] =
                make_float2(v10, v11);
        }
        __syncthreads();

        // ---- online softmax: 2 threads per row, 32 cols each ----
        {
            const int r = tid >> 1, hf = tid & 1;
            float* row = &Ss[r * SS_STRIDE + hf * 32];
            float mx = -3.0e38f;
#pragma unroll
            for (int j = 0; j < 32; j++) mx = fmaxf(mx, row[j]);
            mx = fmaxf(mx, __shfl_xor_sync(0xffffffffu, mx, 1));
            float mold = mrow[r];
            float mnew = fmaxf(mold, mx);
            float sum = 0.f;
#pragma unroll
            for (int j = 0; j < 32; j++) {
                float p = tf32f(__expf(row[j] - mnew));
                row[j] = p;
                sum += p;
            }
            sum += __shfl_xor_sync(0xffffffffu, sum, 1);
            if (hf == 0) {
                float cf = __expf(mold - mnew);
                mrow[r] = mnew;
                lrow[r] = lrow[r] * cf + sum;
                crow[r] = cf;
            }
        }
        __syncthreads();

        // ---- rescale O, accumulate P @ V (warp = 16 rows x 128 cols) ----
        {
            float cf0 = crow[wm * 16 + g], cf1 = crow[wm * 16 + g + 8];
#pragma unroll
            for (int nt = 0; nt < 16; nt++) {
                o[nt][0] *= cf0; o[nt][1] *= cf0;
                o[nt][2] *= cf1; o[nt][3] *= cf1;
            }
        }
#pragma unroll
        for (int ks8 = 0; ks8 < 8; ks8++) {
            const int kk = ks8 * 8;
            uint32_t af[4];
            af[0] = __float_as_uint(Ss[rs0 * SS_STRIDE + kk + tig]);
            af[1] = __float_as_uint(Ss[(rs0 + 8) * SS_STRIDE + kk + tig]);
            af[2] = __float_as_uint(Ss[rs0 * SS_STRIDE + kk + tig + 4]);
            af[3] = __float_as_uint(Ss[(rs0 + 8) * SS_STRIDE + kk + tig + 4]);
#pragma unroll
            for (int nt = 0; nt < 16; nt++) {
                uint32_t b0 = __float_as_uint(vs[(kk + tig) * VS_STRIDE + nt * 8 + g]);
                uint32_t b1 = __float_as_uint(vs[(kk + tig + 4) * VS_STRIDE + nt * 8 + g]);
                mma_tf32(o[nt], af, b0, b1);
            }
        }
    }

    // ---- epilogue: normalize and write (b, t, h, d) ----
    {
        float li0 = 1.f / lrow[wm * 16 + g];
        float li1 = 1.f / lrow[wm * 16 + g + 8];
        float* Og = Ob + ((size_t)(b * SEQ + q0 + wm * 16)) * DMODEL + h * HDIM;
#pragma unroll
        for (int nt = 0; nt < 16; nt++) {
            int c = nt * 8 + 2 * tig;
            *(float2*)&Og[(size_t)g * DMODEL + c] =
                make_float2(o[nt][0] * li0, o[nt][1] * li0);
            *(float2*)&Og[(size_t)(g + 8) * DMODEL + c] =
                make_float2(o[nt][2] * li1, o[nt][3] * li1);
        }
    }
}

// ---------------------------------------------------------------------------
extern "C" void kernel_launch(void* const* d_in, const int* in_sizes, int n_in,
                              void* d_out, int out_size)
{
    (void)in_sizes; (void)n_in; (void)out_size;
    const float* x  = (const float*)d_in[0];
    const float* Wq = (const float*)d_in[1];
    const float* Wk = (const float*)d_in[2];
    const float* Wv = (const float*)d_in[3];
    const float* Wo = (const float*)d_in[4];
    float* out = (float*)d_out;

    float *qp, *kp, *vp, *ap;
    cudaGetSymbolAddress((void**)&qp, g_Q);
    cudaGetSymbolAddress((void**)&kp, g_K);
    cudaGetSymbolAddress((void**)&vp, g_V);
    cudaGetSymbolAddress((void**)&ap, g_A);

    dim3 blk(256);

    cudaFuncSetAttribute(gemm_tf32_kernel,
                         cudaFuncAttributeMaxDynamicSharedMemorySize,
                         GEMM_SMEM_BYTES);
    cudaFuncSetAttribute(gemm_kv_tf32_kernel,
                         cudaFuncAttributeMaxDynamicSharedMemorySize,
                         GEMM_SMEM_BYTES);
    cudaFuncSetAttribute(mqa_kernel,
                         cudaFuncAttributeMaxDynamicSharedMemorySize,
                         ATT_SMEM_BYTES);

    // Q projection
    gemm_tf32_kernel<<<dim3(DMODEL / 128, MROWS / 128), blk, GEMM_SMEM_BYTES>>>(
        x, Wq, qp, MROWS, DMODEL, DMODEL);
    // K and V projections fused
    gemm_kv_tf32_kernel<<<dim3(1, MROWS / 128, 2), blk, GEMM_SMEM_BYTES>>>(
        x, Wk, Wv, kp, vp, MROWS, DMODEL);
    // tensor-core flash attention
    mqa_kernel<<<dim3(SEQ / BQ, NHEADS, BATCH), blk, ATT_SMEM_BYTES>>>(
        qp, kp, vp, ap);
    // output projection
    gemm_tf32_kernel<<<dim3(DMODEL / 128, MROWS / 128), blk, GEMM_SMEM_BYTES>>>(
        ap, Wo, out, MROWS, DMODEL, DMODEL);
}

// round 5
// speedup vs baseline: 4.3384x; 1.2433x over previous
#include <cuda_runtime.h>
#include <cuda_bf16.h>
#include <cstdint>

// Problem constants
#define BATCH   2
#define SEQ     2048
#define DMODEL  2048
#define NHEADS  16
#define HDIM    128
#define MROWS   (BATCH * SEQ)     // 4096

// Scratch (allocation-free rule: __device__ globals) — 86 MB total
__device__ float g_Q[(size_t)MROWS * DMODEL];    // 32 MB (Q, tf32 values)
__device__ float g_K[(size_t)MROWS * HDIM];      //  2 MB
__device__ float g_V[(size_t)MROWS * HDIM];      //  2 MB
__device__ float g_A[(size_t)MROWS * DMODEL];    // 32 MB: xr, then attn out
__device__ float g_W[(size_t)DMODEL * DMODEL];   // 16 MB: Wq rounded, then Wo
__device__ float g_Wk[(size_t)DMODEL * HDIM];    //  1 MB
__device__ float g_Wv[(size_t)DMODEL * HDIM];    //  1 MB

// ---------------------------------------------------------------------------
// tf32 helpers
// ---------------------------------------------------------------------------
__device__ __forceinline__ uint32_t tf32u(float x) {
    uint32_t u;
    asm("cvt.rna.tf32.f32 %0, %1;" : "=r"(u) : "f"(x));
    return u;
}
__device__ __forceinline__ float tf32f(float x) {
    return __uint_as_float(tf32u(x));
}
__device__ __forceinline__ unsigned smem_u32(const void* p) {
    return (unsigned)__cvta_generic_to_shared(p);
}
__device__ __forceinline__ void cp_async16(unsigned dst, const void* src) {
    asm volatile("cp.async.cg.shared.global [%0], [%1], 16;\n"
                 :: "r"(dst), "l"(src));
}
__device__ __forceinline__ void mma_tf32(float c[4], const uint32_t a[4],
                                         uint32_t b0, uint32_t b1) {
    asm volatile(
        "mma.sync.aligned.m16n8k8.row.col.f32.tf32.tf32.f32 "
        "{%0,%1,%2,%3}, {%4,%5,%6,%7}, {%8,%9}, {%0,%1,%2,%3};\n"
        : "+f"(c[0]), "+f"(c[1]), "+f"(c[2]), "+f"(c[3])
        : "r"(a[0]), "r"(a[1]), "r"(a[2]), "r"(a[3]), "r"(b0), "r"(b1));
}

// ---------------------------------------------------------------------------
// elementwise tf32-RN rounding pass
// ---------------------------------------------------------------------------
__global__ void __launch_bounds__(256)
round_kernel(const float* __restrict__ in, float* __restrict__ out, int n4)
{
    int i = blockIdx.x * blockDim.x + threadIdx.x;
    if (i < n4) {
        float4 v = ((const float4*)in)[i];
        v.x = tf32f(v.x); v.y = tf32f(v.y);
        v.z = tf32f(v.z); v.w = tf32f(v.w);
        ((float4*)out)[i] = v;
    }
}

// ---------------------------------------------------------------------------
// tf32 tensor-core GEMM: C[M,N] = A[M,K] @ W[K,N].
// Operands are pre-rounded tf32 values -> NO CVT in mainloop.
// ROUND: tf32-round C at store (for Q/K/V feeding attention).
// ---------------------------------------------------------------------------
#define GS 3
#define AS_STRIDE 36
#define BS_STRIDE 136
#define AS_FLOATS (128 * AS_STRIDE)   // 4608
#define BS_FLOATS (32 * BS_STRIDE)    // 4352
#define GEMM_SMEM_BYTES ((GS * (AS_FLOATS + BS_FLOATS)) * 4)  // 107520

template <bool ROUND>
__device__ __forceinline__ void gemm_tf32_body(
    const float* __restrict__ A, const float* __restrict__ W,
    float* __restrict__ C, int M, int N, int K,
    int bx, int by)
{
    extern __shared__ float sm[];
    float* As = sm;                      // [GS][128][36]
    float* Bs = sm + GS * AS_FLOATS;     // [GS][32][136]

    const int tid  = threadIdx.x;
    const int warp = tid >> 5, lane = tid & 31;
    const int g    = lane >> 2, tig = lane & 3;
    const int wm   = warp >> 2, wn = warp & 3;
    const int row0 = by * 128, col0 = bx * 128;

    float acc[4][4][4];
#pragma unroll
    for (int i = 0; i < 4; i++)
#pragma unroll
        for (int j = 0; j < 4; j++)
#pragma unroll
            for (int r = 0; r < 4; r++) acc[i][j][r] = 0.f;

    const int nk = K / 32;

    auto load_stage = [&](int kb, int s) {
        float* as = As + s * AS_FLOATS;
        float* bs = Bs + s * BS_FLOATS;
#pragma unroll
        for (int i = 0; i < 4; i++) {
            int idx = tid + 256 * i;
            int r = idx >> 3, c4 = (idx & 7) * 4;
            cp_async16(smem_u32(&as[r * AS_STRIDE + c4]),
                       &A[(size_t)(row0 + r) * K + kb * 32 + c4]);
        }
#pragma unroll
        for (int i = 0; i < 4; i++) {
            int idx = tid + 256 * i;
            int r = idx >> 5, c4 = (idx & 31) * 4;
            cp_async16(smem_u32(&bs[r * BS_STRIDE + c4]),
                       &W[(size_t)(kb * 32 + r) * N + col0 + c4]);
        }
        asm volatile("cp.async.commit_group;\n");
    };

#pragma unroll
    for (int s = 0; s < GS - 1; s++) load_stage(s, s);

    for (int kb = 0; kb < nk; kb++) {
        asm volatile("cp.async.wait_group %0;\n" :: "n"(GS - 2));
        __syncthreads();
        if (kb + GS - 1 < nk) load_stage(kb + GS - 1, (kb + GS - 1) % GS);

        const float* as = As + (kb % GS) * AS_FLOATS;
        const float* bs = Bs + (kb % GS) * BS_FLOATS;

#pragma unroll
        for (int ks = 0; ks < 4; ks++) {
            const int kk = ks * 8;
            uint32_t af[4][4], bf[4][2];
#pragma unroll
            for (int i = 0; i < 4; i++) {
                int r = wm * 64 + i * 16 + g;
                af[i][0] = __float_as_uint(as[r * AS_STRIDE + kk + tig]);
                af[i][1] = __float_as_uint(as[(r + 8) * AS_STRIDE + kk + tig]);
                af[i][2] = __float_as_uint(as[r * AS_STRIDE + kk + tig + 4]);
                af[i][3] = __float_as_uint(as[(r + 8) * AS_STRIDE + kk + tig + 4]);
            }
#pragma unroll
            for (int j = 0; j < 4; j++) {
                int c = wn * 32 + j * 8 + g;
                bf[j][0] = __float_as_uint(bs[(kk + tig) * BS_STRIDE + c]);
                bf[j][1] = __float_as_uint(bs[(kk + tig + 4) * BS_STRIDE + c]);
            }
#pragma unroll
            for (int i = 0; i < 4; i++)
#pragma unroll
                for (int j = 0; j < 4; j++)
                    mma_tf32(acc[i][j], af[i], bf[j][0], bf[j][1]);
        }
    }

#pragma unroll
    for (int i = 0; i < 4; i++) {
        int r = row0 + wm * 64 + i * 16 + g;
#pragma unroll
        for (int j = 0; j < 4; j++) {
            int c = col0 + wn * 32 + j * 8 + 2 * tig;
            float v0 = acc[i][j][0], v1 = acc[i][j][1];
            float v2 = acc[i][j][2], v3 = acc[i][j][3];
            if (ROUND) {
                v0 = tf32f(v0); v1 = tf32f(v1);
                v2 = tf32f(v2); v3 = tf32f(v3);
            }
            *(float2*)&C[(size_t)r * N + c]       = make_float2(v0, v1);
            *(float2*)&C[(size_t)(r + 8) * N + c] = make_float2(v2, v3);
        }
    }
}

// Merged Q/K/V projection: grid.x = 18 (16 Q column tiles, 1 K, 1 V)
__global__ void __launch_bounds__(256, 2)
qkv_gemm_kernel(const float* __restrict__ xr,
                const float* __restrict__ wq, const float* __restrict__ wk,
                const float* __restrict__ wv,
                float* __restrict__ Qo, float* __restrict__ Ko,
                float* __restrict__ Vo)
{
    const int bx = blockIdx.x;
    if (bx < 16) {
        gemm_tf32_body<true>(xr, wq, Qo, MROWS, DMODEL, DMODEL, bx, blockIdx.y);
    } else if (bx == 16) {
        gemm_tf32_body<true>(xr, wk, Ko, MROWS, HDIM, DMODEL, 0, blockIdx.y);
    } else {
        gemm_tf32_body<true>(xr, wv, Vo, MROWS, HDIM, DMODEL, 0, blockIdx.y);
    }
}

// Output projection (no rounding of final result)
__global__ void __launch_bounds__(256, 2)
o_gemm_kernel(const float* __restrict__ A, const float* __restrict__ W,
              float* __restrict__ C)
{
    gemm_tf32_body<false>(A, W, C, MROWS, DMODEL, DMODEL,
                          blockIdx.x, blockIdx.y);
}

// ---------------------------------------------------------------------------
// Tensor-core flash MQA, fully register-resident softmax.
// BQ=128, BKV=64, 256 threads (8 warps x 16 query rows).
// Q in registers (tf32). K/V double-buffered cp.async (values already tf32).
// Softmax stats m/l per-thread (rows g, g+8), quad-reduced via shfl.
// P stays in registers; C-frag -> A-frag via shuffle transpose. 1 sync/iter.
// ---------------------------------------------------------------------------
#define BQ   128
#define BKV  64
#define KS_STRIDE 132   // QK B-frag banks = 4g+tig (conflict-free)
#define VS_STRIDE 136   // PV B-frag banks = 8*tig+g (conflict-free)
#define KS_FLOATS (BKV * KS_STRIDE)   // 8448
#define VS_FLOATS (BKV * VS_STRIDE)   // 8704
#define ATT_SMEM_BYTES ((2 * KS_FLOATS + 2 * VS_FLOATS) * 4)   // 137,216 B

__global__ void __launch_bounds__(256)
mqa_kernel(const float* __restrict__ Qb, const float* __restrict__ Kb,
           const float* __restrict__ Vb, float* __restrict__ Ob)
{
    extern __shared__ float sm[];
    float* KsBuf = sm;                        // [2][64][132]
    float* VsBuf = KsBuf + 2 * KS_FLOATS;     // [2][64][136]

    const int tid  = threadIdx.x;
    const int warp = tid >> 5, lane = tid & 31;
    const int g    = lane >> 2, tig = lane & 3;
    const int wm   = warp;
    const int qt   = gridDim.x - 1 - blockIdx.x;   // heavy tiles first
    const int h    = blockIdx.y, b = blockIdx.z;
    const int q0   = qt * BQ;
    const float scale = 0.08838834764831845f;      // 1/sqrt(128)

    // ---- Q fragments in registers (values already tf32; rescale+reround) ----
    uint32_t qreg[16][4];
    {
        const float* Qg = Qb + ((size_t)(b * SEQ + q0 + wm * 16)) * DMODEL
                             + h * HDIM;
#pragma unroll
        for (int ks = 0; ks < 16; ks++) {
            qreg[ks][0] = tf32u(scale * Qg[(size_t)g * DMODEL + ks * 8 + tig]);
            qreg[ks][1] = tf32u(scale * Qg[(size_t)(g + 8) * DMODEL + ks * 8 + tig]);
            qreg[ks][2] = tf32u(scale * Qg[(size_t)g * DMODEL + ks * 8 + tig + 4]);
            qreg[ks][3] = tf32u(scale * Qg[(size_t)(g + 8) * DMODEL + ks * 8 + tig + 4]);
        }
    }

    float o[16][4];
#pragma unroll
    for (int nt = 0; nt < 16; nt++)
#pragma unroll
        for (int r = 0; r < 4; r++) o[nt][r] = 0.f;

    float m0 = -3.0e38f, m1 = -3.0e38f;   // running max, rows g / g+8
    float l0 = 0.f, l1 = 0.f;             // running denom

    const int nkb = 2 * qt + 2;           // causal: key blocks 0 .. 2*qt+1

    auto load_kv = [&](int kb) {
        const int buf = kb & 1;
        const float* Kg = Kb + ((size_t)(b * SEQ + kb * BKV)) * HDIM;
        const float* Vg = Vb + ((size_t)(b * SEQ + kb * BKV)) * HDIM;
        float* ks = KsBuf + buf * KS_FLOATS;
        float* vs = VsBuf + buf * VS_FLOATS;
#pragma unroll
        for (int i = 0; i < 8; i++) {
            int idx = tid + 256 * i;      // 2048 float4 = 64 rows x 32
            int r = idx >> 5, c4 = (idx & 31) * 4;
            cp_async16(smem_u32(&ks[r * KS_STRIDE + c4]),
                       &Kg[(size_t)r * HDIM + c4]);
            cp_async16(smem_u32(&vs[r * VS_STRIDE + c4]),
                       &Vg[(size_t)r * HDIM + c4]);
        }
        asm volatile("cp.async.commit_group;\n");
    };

    load_kv(0);

    for (int kb = 0; kb < nkb; kb++) {
        const int k0 = kb * BKV;
        asm volatile("cp.async.wait_group 0;\n");
        __syncthreads();
        if (kb + 1 < nkb) load_kv(kb + 1);

        const float* ks = KsBuf + (kb & 1) * KS_FLOATS;
        const float* vs = VsBuf + (kb & 1) * VS_FLOATS;

        // ---- S = Q K^T (warp: 16 rows x 64 cols, 8 n-tiles) ----
        float sacc[8][4];
#pragma unroll
        for (int j = 0; j < 8; j++)
#pragma unroll
            for (int r = 0; r < 4; r++) sacc[j][r] = 0.f;

#pragma unroll
        for (int ks4 = 0; ks4 < 16; ks4++) {
            const int kk = ks4 * 8;
            uint32_t bf[8][2];
#pragma unroll
            for (int j = 0; j < 8; j++) {
                bf[j][0] = __float_as_uint(ks[(j * 8 + g) * KS_STRIDE + kk + tig]);
                bf[j][1] = __float_as_uint(ks[(j * 8 + g) * KS_STRIDE + kk + tig + 4]);
            }
#pragma unroll
            for (int j = 0; j < 8; j++)
                mma_tf32(sacc[j], qreg[ks4], bf[j][0], bf[j][1]);
        }

        // ---- causal mask in registers ----
        const bool needs_mask = (k0 + BKV - 1 > q0);
        const int rg0 = q0 + wm * 16 + g, rg1 = rg0 + 8;
        if (needs_mask) {
#pragma unroll
            for (int j = 0; j < 8; j++) {
                int cg = k0 + j * 8 + 2 * tig;
                if (cg     > rg0) sacc[j][0] = -3.0e38f;
                if (cg + 1 > rg0) sacc[j][1] = -3.0e38f;
                if (cg     > rg1) sacc[j][2] = -3.0e38f;
                if (cg + 1 > rg1) sacc[j][3] = -3.0e38f;
            }
        }

        // ---- register softmax (quad shfl reductions) ----
        float mx0 = -3.0e38f, mx1 = -3.0e38f;
#pragma unroll
        for (int j = 0; j < 8; j++) {
            mx0 = fmaxf(mx0, fmaxf(sacc[j][0], sacc[j][1]));
            mx1 = fmaxf(mx1, fmaxf(sacc[j][2], sacc[j][3]));
        }
        mx0 = fmaxf(mx0, __shfl_xor_sync(0xffffffffu, mx0, 1));
        mx0 = fmaxf(mx0, __shfl_xor_sync(0xffffffffu, mx0, 2));
        mx1 = fmaxf(mx1, __shfl_xor_sync(0xffffffffu, mx1, 1));
        mx1 = fmaxf(mx1, __shfl_xor_sync(0xffffffffu, mx1, 2));

        float mn0 = fmaxf(m0, mx0), mn1 = fmaxf(m1, mx1);
        float cf0 = __expf(m0 - mn0), cf1 = __expf(m1 - mn1);
        m0 = mn0; m1 = mn1;

        float s0 = 0.f, s1 = 0.f;
#pragma unroll
        for (int j = 0; j < 8; j++) {
            float p0 = tf32f(__expf(sacc[j][0] - mn0));
            float p1 = tf32f(__expf(sacc[j][1] - mn0));
            float p2 = tf32f(__expf(sacc[j][2] - mn1));
            float p3 = tf32f(__expf(sacc[j][3] - mn1));
            sacc[j][0] = p0; sacc[j][1] = p1;
            sacc[j][2] = p2; sacc[j][3] = p3;
            s0 += p0 + p1;
            s1 += p2 + p3;
        }
        s0 += __shfl_xor_sync(0xffffffffu, s0, 1);
        s0 += __shfl_xor_sync(0xffffffffu, s0, 2);
        s1 += __shfl_xor_sync(0xffffffffu, s1, 1);
        s1 += __shfl_xor_sync(0xffffffffu, s1, 2);
        l0 = l0 * cf0 + s0;
        l1 = l1 * cf1 + s1;

#pragma unroll
        for (int nt = 0; nt < 16; nt++) {
            o[nt][0] *= cf0; o[nt][1] *= cf0;
            o[nt][2] *= cf1; o[nt][3] *= cf1;
        }

        // ---- PV: shuffle-transpose C-frag P -> A-frag, then mma ----
        const unsigned src1 = (lane & ~3u) | ((unsigned)tig >> 1);
        const unsigned src2 = src1 + 2;
        const bool e = tig & 1;
#pragma unroll
        for (int j = 0; j < 8; j++) {
            float v0 = __shfl_sync(0xffffffffu, sacc[j][0], src1);
            float v1 = __shfl_sync(0xffffffffu, sacc[j][1], src1);
            float v2 = __shfl_sync(0xffffffffu, sacc[j][2], src1);
            float v3 = __shfl_sync(0xffffffffu, sacc[j][3], src1);
            float w0 = __shfl_sync(0xffffffffu, sacc[j][0], src2);
            float w1 = __shfl_sync(0xffffffffu, sacc[j][1], src2);
            float w2 = __shfl_sync(0xffffffffu, sacc[j][2], src2);
            float w3 = __shfl_sync(0xffffffffu, sacc[j][3], src2);
            uint32_t af[4];
            af[0] = __float_as_uint(e ? v1 : v0);   // (g,    j*8+tig)
            af[1] = __float_as_uint(e ? v3 : v2);   // (g+8,  j*8+tig)
            af[2] = __float_as_uint(e ? w1 : w0);   // (g,    j*8+tig+4)
            af[3] = __float_as_uint(e ? w3 : w2);   // (g+8,  j*8+tig+4)

            const int kk = j * 8;
#pragma unroll
            for (int nt = 0; nt < 16; nt++) {
                uint32_t b0 = __float_as_uint(vs[(kk + tig) * VS_STRIDE + nt * 8 + g]);
                uint32_t b1 = __float_as_uint(vs[(kk + tig + 4) * VS_STRIDE + nt * 8 + g]);
                mma_tf32(o[nt], af, b0, b1);
            }
        }
    }

    // ---- epilogue: normalize and write (b, t, h, d) ----
    {
        float li0 = 1.f / l0, li1 = 1.f / l1;
        float* Og = Ob + ((size_t)(b * SEQ + q0 + wm * 16)) * DMODEL + h * HDIM;
#pragma unroll
        for (int nt = 0; nt < 16; nt++) {
            int c = nt * 8 + 2 * tig;
            *(float2*)&Og[(size_t)g * DMODEL + c] =
                make_float2(tf32f(o[nt][0] * li0), tf32f(o[nt][1] * li0));
            *(float2*)&Og[(size_t)(g + 8) * DMODEL + c] =
                make_float2(tf32f(o[nt][2] * li1), tf32f(o[nt][3] * li1));
        }
    }
}

// ---------------------------------------------------------------------------
extern "C" void kernel_launch(void* const* d_in, const int* in_sizes, int n_in,
                              void* d_out, int out_size)
{
    (void)in_sizes; (void)n_in; (void)out_size;
    const float* x  = (const float*)d_in[0];
    const float* Wq = (const float*)d_in[1];
    const float* Wk = (const float*)d_in[2];
    const float* Wv = (const float*)d_in[3];
    const float* Wo = (const float*)d_in[4];
    float* out = (float*)d_out;

    float *qp, *kp, *vp, *ap, *wp, *wkp, *wvp;
    cudaGetSymbolAddress((void**)&qp,  g_Q);
    cudaGetSymbolAddress((void**)&kp,  g_K);
    cudaGetSymbolAddress((void**)&vp,  g_V);
    cudaGetSymbolAddress((void**)&ap,  g_A);
    cudaGetSymbolAddress((void**)&wp,  g_W);
    cudaGetSymbolAddress((void**)&wkp, g_Wk);
    cudaGetSymbolAddress((void**)&wvp, g_Wv);

    dim3 blk(256);

    cudaFuncSetAttribute(qkv_gemm_kernel,
                         cudaFuncAttributeMaxDynamicSharedMemorySize,
                         GEMM_SMEM_BYTES);
    cudaFuncSetAttribute(o_gemm_kernel,
                         cudaFuncAttributeMaxDynamicSharedMemorySize,
                         GEMM_SMEM_BYTES);
    cudaFuncSetAttribute(mqa_kernel,
                         cudaFuncAttributeMaxDynamicSharedMemorySize,
                         ATT_SMEM_BYTES);

    const int n4x = MROWS * DMODEL / 4;
    const int n4w = DMODEL * DMODEL / 4;
    const int n4k = DMODEL * HDIM / 4;

    // Pre-round GEMM inputs to tf32 (RN). xr lives in g_A until attention.
    round_kernel<<<(n4x + 255) / 256, blk>>>(x,  ap,  n4x);
    round_kernel<<<(n4w + 255) / 256, blk>>>(Wq, wp,  n4w);
    round_kernel<<<(n4k + 255) / 256, blk>>>(Wk, wkp, n4k);
    round_kernel<<<(n4k + 255) / 256, blk>>>(Wv, wvp, n4k);

    // Fused Q/K/V projection (epilogue rounds outputs to tf32)
    qkv_gemm_kernel<<<dim3(18, MROWS / 128), blk, GEMM_SMEM_BYTES>>>(
        ap, wp, wkp, wvp, qp, kp, vp);

    // Round Wo into the (now free) weight buffer
    round_kernel<<<(n4w + 255) / 256, blk>>>(Wo, wp, n4w);

    // Flash attention (overwrites g_A with tf32-rounded attention output)
    mqa_kernel<<<dim3(SEQ / BQ, NHEADS, BATCH), blk, ATT_SMEM_BYTES>>>(
        qp, kp, vp, ap);

    // Output projection (fp32 result)
    o_gemm_kernel<<<dim3(DMODEL / 128, MROWS / 128), blk, GEMM_SMEM_BYTES>>>(
        ap, wp, out);
}

// round 6
// speedup vs baseline: 4.5240x; 1.0428x over previous
#include <cuda_runtime.h>
#include <cuda_bf16.h>
#include <cstdint>

// Problem constants
#define BATCH   2
#define SEQ     2048
#define DMODEL  2048
#define NHEADS  16
#define HDIM    128
#define MROWS   (BATCH * SEQ)     // 4096

// Scratch (allocation-free rule: __device__ globals) — 86 MB total
__device__ float g_Q[(size_t)MROWS * DMODEL];    // 32 MB (Q, tf32 values)
__device__ float g_K[(size_t)MROWS * HDIM];      //  2 MB
__device__ float g_V[(size_t)MROWS * HDIM];      //  2 MB
__device__ float g_A[(size_t)MROWS * DMODEL];    // 32 MB: xr, then attn out
__device__ float g_W[(size_t)DMODEL * DMODEL];   // 16 MB: Wq rounded, then Wo
__device__ float g_Wk[(size_t)DMODEL * HDIM];    //  1 MB
__device__ float g_Wv[(size_t)DMODEL * HDIM];    //  1 MB

// ---------------------------------------------------------------------------
// tf32 helpers
// ---------------------------------------------------------------------------
__device__ __forceinline__ uint32_t tf32u(float x) {
    uint32_t u;
    asm("cvt.rna.tf32.f32 %0, %1;" : "=r"(u) : "f"(x));
    return u;
}
__device__ __forceinline__ float tf32f(float x) {
    return __uint_as_float(tf32u(x));
}
__device__ __forceinline__ unsigned smem_u32(const void* p) {
    return (unsigned)__cvta_generic_to_shared(p);
}
__device__ __forceinline__ void cp_async16(unsigned dst, const void* src) {
    asm volatile("cp.async.cg.shared.global [%0], [%1], 16;\n"
                 :: "r"(dst), "l"(src));
}
__device__ __forceinline__ void mma_tf32(float c[4], const uint32_t a[4],
                                         uint32_t b0, uint32_t b1) {
    asm volatile(
        "mma.sync.aligned.m16n8k8.row.col.f32.tf32.tf32.f32 "
        "{%0,%1,%2,%3}, {%4,%5,%6,%7}, {%8,%9}, {%0,%1,%2,%3};\n"
        : "+f"(c[0]), "+f"(c[1]), "+f"(c[2]), "+f"(c[3])
        : "r"(a[0]), "r"(a[1]), "r"(a[2]), "r"(a[3]), "r"(b0), "r"(b1));
}
__device__ __forceinline__ void ldsm_x4(uint32_t r[4], unsigned addr) {
    asm volatile(
        "ldmatrix.sync.aligned.m8n8.x4.shared.b16 {%0,%1,%2,%3}, [%4];\n"
        : "=r"(r[0]), "=r"(r[1]), "=r"(r[2]), "=r"(r[3])
        : "r"(addr));
}

// ---------------------------------------------------------------------------
// Batched elementwise tf32-RN rounding: x (8192 blks), Wq (4096), Wk (256),
// Wv (256) in ONE launch. Each block rounds 256 float4.
// ---------------------------------------------------------------------------
__global__ void __launch_bounds__(256)
round4_kernel(const float* __restrict__ x,  float* __restrict__ xr,
              const float* __restrict__ wq, float* __restrict__ wqr,
              const float* __restrict__ wk, float* __restrict__ wkr,
              const float* __restrict__ wv, float* __restrict__ wvr)
{
    int bb = blockIdx.x;
    const float4* src;
    float4* dst;
    if (bb < 8192)       { src = (const float4*)x  + (size_t)bb * 256;
                           dst = (float4*)xr       + (size_t)bb * 256; }
    else if (bb < 12288) { bb -= 8192;
                           src = (const float4*)wq + (size_t)bb * 256;
                           dst = (float4*)wqr      + (size_t)bb * 256; }
    else if (bb < 12544) { bb -= 12288;
                           src = (const float4*)wk + (size_t)bb * 256;
                           dst = (float4*)wkr      + (size_t)bb * 256; }
    else                 { bb -= 12544;
                           src = (const float4*)wv + (size_t)bb * 256;
                           dst = (float4*)wvr      + (size_t)bb * 256; }
    float4 v = src[threadIdx.x];
    v.x = tf32f(v.x); v.y = tf32f(v.y);
    v.z = tf32f(v.z); v.w = tf32f(v.w);
    dst[threadIdx.x] = v;
}

__global__ void __launch_bounds__(256)
round_kernel(const float* __restrict__ in, float* __restrict__ out, int n4)
{
    int i = blockIdx.x * blockDim.x + threadIdx.x;
    if (i < n4) {
        float4 v = ((const float4*)in)[i];
        v.x = tf32f(v.x); v.y = tf32f(v.y);
        v.z = tf32f(v.z); v.w = tf32f(v.w);
        ((float4*)out)[i] = v;
    }
}

// ---------------------------------------------------------------------------
// tf32 tensor-core GEMM: C[M,N] = A[M,K] @ W[K,N].
// Operands pre-rounded tf32. A-fragments via ldmatrix.x4 (16 LDSM replaces
// 64 LDS per warp per k-block). ROUND: tf32-round C at store.
// ---------------------------------------------------------------------------
#define GS 3
#define AS_STRIDE 36
#define BS_STRIDE 136
#define AS_FLOATS (128 * AS_STRIDE)   // 4608
#define BS_FLOATS (32 * BS_STRIDE)    // 4352
#define GEMM_SMEM_BYTES ((GS * (AS_FLOATS + BS_FLOATS)) * 4)  // 107520

template <bool ROUND>
__device__ __forceinline__ void gemm_tf32_body(
    const float* __restrict__ A, const float* __restrict__ W,
    float* __restrict__ C, int M, int N, int K,
    int bx, int by)
{
    extern __shared__ float sm[];
    float* As = sm;                      // [GS][128][36]
    float* Bs = sm + GS * AS_FLOATS;     // [GS][32][136]

    const int tid  = threadIdx.x;
    const int warp = tid >> 5, lane = tid & 31;
    const int g    = lane >> 2, tig = lane & 3;
    const int wm   = warp >> 2, wn = warp & 3;
    const int row0 = by * 128, col0 = bx * 128;

    // per-lane ldmatrix row/col offset (element units) within an A stage:
    // row = wm*64 + i*16 + (lane&15), col = kk + 4*(lane>>4)
    const unsigned lm_off =
        (unsigned)((wm * 64 + (lane & 15)) * AS_STRIDE + 4 * (lane >> 4));

    float acc[4][4][4];
#pragma unroll
    for (int i = 0; i < 4; i++)
#pragma unroll
        for (int j = 0; j < 4; j++)
#pragma unroll
            for (int r = 0; r < 4; r++) acc[i][j][r] = 0.f;

    const int nk = K / 32;

    auto load_stage = [&](int kb, int s) {
        float* as = As + s * AS_FLOATS;
        float* bs = Bs + s * BS_FLOATS;
#pragma unroll
        for (int i = 0; i < 4; i++) {
            int idx = tid + 256 * i;
            int r = idx >> 3, c4 = (idx & 7) * 4;
            cp_async16(smem_u32(&as[r * AS_STRIDE + c4]),
                       &A[(size_t)(row0 + r) * K + kb * 32 + c4]);
        }
#pragma unroll
        for (int i = 0; i < 4; i++) {
            int idx = tid + 256 * i;
            int r = idx >> 5, c4 = (idx & 31) * 4;
            cp_async16(smem_u32(&bs[r * BS_STRIDE + c4]),
                       &W[(size_t)(kb * 32 + r) * N + col0 + c4]);
        }
        asm volatile("cp.async.commit_group;\n");
    };

#pragma unroll
    for (int s = 0; s < GS - 1; s++) load_stage(s, s);

    for (int kb = 0; kb < nk; kb++) {
        asm volatile("cp.async.wait_group %0;\n" :: "n"(GS - 2));
        __syncthreads();
        if (kb + GS - 1 < nk) load_stage(kb + GS - 1, (kb + GS - 1) % GS);

        const float* bs = Bs + (kb % GS) * BS_FLOATS;
        const unsigned as_base =
            smem_u32(As + (kb % GS) * AS_FLOATS) + lm_off * 4u;

#pragma unroll
        for (int ks = 0; ks < 4; ks++) {
            const int kk = ks * 8;
            uint32_t af[4][4], bf[4][2];
#pragma unroll
            for (int i = 0; i < 4; i++)
                ldsm_x4(af[i], as_base + (unsigned)(i * 16 * AS_STRIDE + kk) * 4u);
#pragma unroll
            for (int j = 0; j < 4; j++) {
                int c = wn * 32 + j * 8 + g;
                bf[j][0] = __float_as_uint(bs[(kk + tig) * BS_STRIDE + c]);
                bf[j][1] = __float_as_uint(bs[(kk + tig + 4) * BS_STRIDE + c]);
            }
#pragma unroll
            for (int i = 0; i < 4; i++)
#pragma unroll
                for (int j = 0; j < 4; j++)
                    mma_tf32(acc[i][j], af[i], bf[j][0], bf[j][1]);
        }
    }

#pragma unroll
    for (int i = 0; i < 4; i++) {
        int r = row0 + wm * 64 + i * 16 + g;
#pragma unroll
        for (int j = 0; j < 4; j++) {
            int c = col0 + wn * 32 + j * 8 + 2 * tig;
            float v0 = acc[i][j][0], v1 = acc[i][j][1];
            float v2 = acc[i][j][2], v3 = acc[i][j][3];
            if (ROUND) {
                v0 = tf32f(v0); v1 = tf32f(v1);
                v2 = tf32f(v2); v3 = tf32f(v3);
            }
            *(float2*)&C[(size_t)r * N + c]       = make_float2(v0, v1);
            *(float2*)&C[(size_t)(r + 8) * N + c] = make_float2(v2, v3);
        }
    }
}

// Merged Q/K/V projection: grid.x = 18 (16 Q column tiles, 1 K, 1 V)
__global__ void __launch_bounds__(256, 2)
qkv_gemm_kernel(const float* __restrict__ xr,
                const float* __restrict__ wq, const float* __restrict__ wk,
                const float* __restrict__ wv,
                float* __restrict__ Qo, float* __restrict__ Ko,
                float* __restrict__ Vo)
{
    const int bx = blockIdx.x;
    if (bx < 16) {
        gemm_tf32_body<true>(xr, wq, Qo, MROWS, DMODEL, DMODEL, bx, blockIdx.y);
    } else if (bx == 16) {
        gemm_tf32_body<true>(xr, wk, Ko, MROWS, HDIM, DMODEL, 0, blockIdx.y);
    } else {
        gemm_tf32_body<true>(xr, wv, Vo, MROWS, HDIM, DMODEL, 0, blockIdx.y);
    }
}

// Output projection (no rounding of final result)
__global__ void __launch_bounds__(256, 2)
o_gemm_kernel(const float* __restrict__ A, const float* __restrict__ W,
              float* __restrict__ C)
{
    gemm_tf32_body<false>(A, W, C, MROWS, DMODEL, DMODEL,
                          blockIdx.x, blockIdx.y);
}

// ---------------------------------------------------------------------------
// Tensor-core flash MQA, fully register-resident softmax (round-5, unchanged).
// ---------------------------------------------------------------------------
#define BQ   128
#define BKV  64
#define KS_STRIDE 132
#define VS_STRIDE 136
#define KS_FLOATS (BKV * KS_STRIDE)   // 8448
#define VS_FLOATS (BKV * VS_STRIDE)   // 8704
#define ATT_SMEM_BYTES ((2 * KS_FLOATS + 2 * VS_FLOATS) * 4)   // 137,216 B

__global__ void __launch_bounds__(256)
mqa_kernel(const float* __restrict__ Qb, const float* __restrict__ Kb,
           const float* __restrict__ Vb, float* __restrict__ Ob)
{
    extern __shared__ float sm[];
    float* KsBuf = sm;                        // [2][64][132]
    float* VsBuf = KsBuf + 2 * KS_FLOATS;     // [2][64][136]

    const int tid  = threadIdx.x;
    const int warp = tid >> 5, lane = tid & 31;
    const int g    = lane >> 2, tig = lane & 3;
    const int wm   = warp;
    const int qt   = gridDim.x - 1 - blockIdx.x;   // heavy tiles first
    const int h    = blockIdx.y, b = blockIdx.z;
    const int q0   = qt * BQ;
    const float scale = 0.08838834764831845f;      // 1/sqrt(128)

    uint32_t qreg[16][4];
    {
        const float* Qg = Qb + ((size_t)(b * SEQ + q0 + wm * 16)) * DMODEL
                             + h * HDIM;
#pragma unroll
        for (int ks = 0; ks < 16; ks++) {
            qreg[ks][0] = tf32u(scale * Qg[(size_t)g * DMODEL + ks * 8 + tig]);
            qreg[ks][1] = tf32u(scale * Qg[(size_t)(g + 8) * DMODEL + ks * 8 + tig]);
            qreg[ks][2] = tf32u(scale * Qg[(size_t)g * DMODEL + ks * 8 + tig + 4]);
            qreg[ks][3] = tf32u(scale * Qg[(size_t)(g + 8) * DMODEL + ks * 8 + tig + 4]);
        }
    }

    float o[16][4];
#pragma unroll
    for (int nt = 0; nt < 16; nt++)
#pragma unroll
        for (int r = 0; r < 4; r++) o[nt][r] = 0.f;

    float m0 = -3.0e38f, m1 = -3.0e38f;
    float l0 = 0.f, l1 = 0.f;

    const int nkb = 2 * qt + 2;

    auto load_kv = [&](int kb) {
        const int buf = kb & 1;
        const float* Kg = Kb + ((size_t)(b * SEQ + kb * BKV)) * HDIM;
        const float* Vg = Vb + ((size_t)(b * SEQ + kb * BKV)) * HDIM;
        float* ks = KsBuf + buf * KS_FLOATS;
        float* vs = VsBuf + buf * VS_FLOATS;
#pragma unroll
        for (int i = 0; i < 8; i++) {
            int idx = tid + 256 * i;
            int r = idx >> 5, c4 = (idx & 31) * 4;
            cp_async16(smem_u32(&ks[r * KS_STRIDE + c4]),
                       &Kg[(size_t)r * HDIM + c4]);
            cp_async16(smem_u32(&vs[r * VS_STRIDE + c4]),
                       &Vg[(size_t)r * HDIM + c4]);
        }
        asm volatile("cp.async.commit_group;\n");
    };

    load_kv(0);

    for (int kb = 0; kb < nkb; kb++) {
        const int k0 = kb * BKV;
        asm volatile("cp.async.wait_group 0;\n");
        __syncthreads();
        if (kb + 1 < nkb) load_kv(kb + 1);

        const float* ks = KsBuf + (kb & 1) * KS_FLOATS;
        const float* vs = VsBuf + (kb & 1) * VS_FLOATS;

        float sacc[8][4];
#pragma unroll
        for (int j = 0; j < 8; j++)
#pragma unroll
            for (int r = 0; r < 4; r++) sacc[j][r] = 0.f;

#pragma unroll
        for (int ks4 = 0; ks4 < 16; ks4++) {
            const int kk = ks4 * 8;
            uint32_t bf[8][2];
#pragma unroll
            for (int j = 0; j < 8; j++) {
                bf[j][0] = __float_as_uint(ks[(j * 8 + g) * KS_STRIDE + kk + tig]);
                bf[j][1] = __float_as_uint(ks[(j * 8 + g) * KS_STRIDE + kk + tig + 4]);
            }
#pragma unroll
            for (int j = 0; j < 8; j++)
                mma_tf32(sacc[j], qreg[ks4], bf[j][0], bf[j][1]);
        }

        const bool needs_mask = (k0 + BKV - 1 > q0);
        const int rg0 = q0 + wm * 16 + g, rg1 = rg0 + 8;
        if (needs_mask) {
#pragma unroll
            for (int j = 0; j < 8; j++) {
                int cg = k0 + j * 8 + 2 * tig;
                if (cg     > rg0) sacc[j][0] = -3.0e38f;
                if (cg + 1 > rg0) sacc[j][1] = -3.0e38f;
                if (cg     > rg1) sacc[j][2] = -3.0e38f;
                if (cg + 1 > rg1) sacc[j][3] = -3.0e38f;
            }
        }

        float mx0 = -3.0e38f, mx1 = -3.0e38f;
#pragma unroll
        for (int j = 0; j < 8; j++) {
            mx0 = fmaxf(mx0, fmaxf(sacc[j][0], sacc[j][1]));
            mx1 = fmaxf(mx1, fmaxf(sacc[j][2], sacc[j][3]));
        }
        mx0 = fmaxf(mx0, __shfl_xor_sync(0xffffffffu, mx0, 1));
        mx0 = fmaxf(mx0, __shfl_xor_sync(0xffffffffu, mx0, 2));
        mx1 = fmaxf(mx1, __shfl_xor_sync(0xffffffffu, mx1, 1));
        mx1 = fmaxf(mx1, __shfl_xor_sync(0xffffffffu, mx1, 2));

        float mn0 = fmaxf(m0, mx0), mn1 = fmaxf(m1, mx1);
        float cf0 = __expf(m0 - mn0), cf1 = __expf(m1 - mn1);
        m0 = mn0; m1 = mn1;

        float s0 = 0.f, s1 = 0.f;
#pragma unroll
        for (int j = 0; j < 8; j++) {
            float p0 = tf32f(__expf(sacc[j][0] - mn0));
            float p1 = tf32f(__expf(sacc[j][1] - mn0));
            float p2 = tf32f(__expf(sacc[j][2] - mn1));
            float p3 = tf32f(__expf(sacc[j][3] - mn1));
            sacc[j][0] = p0; sacc[j][1] = p1;
            sacc[j][2] = p2; sacc[j][3] = p3;
            s0 += p0 + p1;
            s1 += p2 + p3;
        }
        s0 += __shfl_xor_sync(0xffffffffu, s0, 1);
        s0 += __shfl_xor_sync(0xffffffffu, s0, 2);
        s1 += __shfl_xor_sync(0xffffffffu, s1, 1);
        s1 += __shfl_xor_sync(0xffffffffu, s1, 2);
        l0 = l0 * cf0 + s0;
        l1 = l1 * cf1 + s1;

#pragma unroll
        for (int nt = 0; nt < 16; nt++) {
            o[nt][0] *= cf0; o[nt][1] *= cf0;
            o[nt][2] *= cf1; o[nt][3] *= cf1;
        }

        const unsigned src1 = (lane & ~3u) | ((unsigned)tig >> 1);
        const unsigned src2 = src1 + 2;
        const bool e = tig & 1;
#pragma unroll
        for (int j = 0; j < 8; j++) {
            float v0 = __shfl_sync(0xffffffffu, sacc[j][0], src1);
            float v1 = __shfl_sync(0xffffffffu, sacc[j][1], src1);
            float v2 = __shfl_sync(0xffffffffu, sacc[j][2], src1);
            float v3 = __shfl_sync(0xffffffffu, sacc[j][3], src1);
            float w0 = __shfl_sync(0xffffffffu, sacc[j][0], src2);
            float w1 = __shfl_sync(0xffffffffu, sacc[j][1], src2);
            float w2 = __shfl_sync(0xffffffffu, sacc[j][2], src2);
            float w3 = __shfl_sync(0xffffffffu, sacc[j][3], src2);
            uint32_t af[4];
            af[0] = __float_as_uint(e ? v1 : v0);
            af[1] = __float_as_uint(e ? v3 : v2);
            af[2] = __float_as_uint(e ? w1 : w0);
            af[3] = __float_as_uint(e ? w3 : w2);

            const int kk = j * 8;
#pragma unroll
            for (int nt = 0; nt < 16; nt++) {
                uint32_t b0 = __float_as_uint(vs[(kk + tig) * VS_STRIDE + nt * 8 + g]);
                uint32_t b1 = __float_as_uint(vs[(kk + tig + 4) * VS_STRIDE + nt * 8 + g]);
                mma_tf32(o[nt], af, b0, b1);
            }
        }
    }

    {
        float li0 = 1.f / l0, li1 = 1.f / l1;
        float* Og = Ob + ((size_t)(b * SEQ + q0 + wm * 16)) * DMODEL + h * HDIM;
#pragma unroll
        for (int nt = 0; nt < 16; nt++) {
            int c = nt * 8 + 2 * tig;
            *(float2*)&Og[(size_t)g * DMODEL + c] =
                make_float2(tf32f(o[nt][0] * li0), tf32f(o[nt][1] * li0));
            *(float2*)&Og[(size_t)(g + 8) * DMODEL + c] =
                make_float2(tf32f(o[nt][2] * li1), tf32f(o[nt][3] * li1));
        }
    }
}

// ---------------------------------------------------------------------------
extern "C" void kernel_launch(void* const* d_in, const int* in_sizes, int n_in,
                              void* d_out, int out_size)
{
    (void)in_sizes; (void)n_in; (void)out_size;
    const float* x  = (const float*)d_in[0];
    const float* Wq = (const float*)d_in[1];
    const float* Wk = (const float*)d_in[2];
    const float* Wv = (const float*)d_in[3];
    const float* Wo = (const float*)d_in[4];
    float* out = (float*)d_out;

    float *qp, *kp, *vp, *ap, *wp, *wkp, *wvp;
    cudaGetSymbolAddress((void**)&qp,  g_Q);
    cudaGetSymbolAddress((void**)&kp,  g_K);
    cudaGetSymbolAddress((void**)&vp,  g_V);
    cudaGetSymbolAddress((void**)&ap,  g_A);
    cudaGetSymbolAddress((void**)&wp,  g_W);
    cudaGetSymbolAddress((void**)&wkp, g_Wk);
    cudaGetSymbolAddress((void**)&wvp, g_Wv);

    dim3 blk(256);

    cudaFuncSetAttribute(qkv_gemm_kernel,
                         cudaFuncAttributeMaxDynamicSharedMemorySize,
                         GEMM_SMEM_BYTES);
    cudaFuncSetAttribute(o_gemm_kernel,
                         cudaFuncAttributeMaxDynamicSharedMemorySize,
                         GEMM_SMEM_BYTES);
    cudaFuncSetAttribute(mqa_kernel,
                         cudaFuncAttributeMaxDynamicSharedMemorySize,
                         ATT_SMEM_BYTES);

    // Pre-round x, Wq, Wk, Wv in ONE launch (xr lives in g_A until attention)
    round4_kernel<<<12800, blk>>>(x, ap, Wq, wp, Wk, wkp, Wv, wvp);

    // Fused Q/K/V projection (epilogue rounds outputs to tf32)
    qkv_gemm_kernel<<<dim3(18, MROWS / 128), blk, GEMM_SMEM_BYTES>>>(
        ap, wp, wkp, wvp, qp, kp, vp);

    // Round Wo into the (now free) weight buffer
    round_kernel<<<(DMODEL * DMODEL / 4 + 255) / 256, blk>>>(
        Wo, wp, DMODEL * DMODEL / 4);

    // Flash attention (overwrites g_A with tf32-rounded attention output)
    mqa_kernel<<<dim3(SEQ / BQ, NHEADS, BATCH), blk, ATT_SMEM_BYTES>>>(
        qp, kp, vp, ap);

    // Output projection (fp32 result)
    o_gemm_kernel<<<dim3(DMODEL / 128, MROWS / 128), blk, GEMM_SMEM_BYTES>>>(
        ap, wp, out);
}

// round 7
// speedup vs baseline: 4.6661x; 1.0314x over previous
#include <cuda_runtime.h>
#include <cuda_bf16.h>
#include <cstdint>

// Problem constants
#define BATCH   2
#define SEQ     2048
#define DMODEL  2048
#define NHEADS  16
#define HDIM    128
#define MROWS   (BATCH * SEQ)     // 4096

// Scratch (allocation-free rule: __device__ globals) — 86 MB total
__device__ float g_Q[(size_t)MROWS * DMODEL];    // 32 MB (Q, tf32 values)
__device__ float g_K[(size_t)MROWS * HDIM];      //  2 MB (K, token-major)
__device__ float g_V[(size_t)MROWS * HDIM];      //  2 MB (V^T: [HDIM][MROWS])
__device__ float g_A[(size_t)MROWS * DMODEL];    // 32 MB: xr, then attn out
__device__ float g_W[(size_t)DMODEL * DMODEL];   // 16 MB: Wq rounded, then Wo
__device__ float g_Wk[(size_t)DMODEL * HDIM];    //  1 MB
__device__ float g_Wv[(size_t)DMODEL * HDIM];    //  1 MB

// ---------------------------------------------------------------------------
// tf32 helpers
// ---------------------------------------------------------------------------
__device__ __forceinline__ uint32_t tf32u(float x) {
    uint32_t u;
    asm("cvt.rna.tf32.f32 %0, %1;" : "=r"(u) : "f"(x));
    return u;
}
__device__ __forceinline__ float tf32f(float x) {
    return __uint_as_float(tf32u(x));
}
__device__ __forceinline__ unsigned smem_u32(const void* p) {
    return (unsigned)__cvta_generic_to_shared(p);
}
__device__ __forceinline__ void cp_async16(unsigned dst, const void* src) {
    asm volatile("cp.async.cg.shared.global [%0], [%1], 16;\n"
                 :: "r"(dst), "l"(src));
}
__device__ __forceinline__ void mma_tf32(float c[4], const uint32_t a[4],
                                         uint32_t b0, uint32_t b1) {
    asm volatile(
        "mma.sync.aligned.m16n8k8.row.col.f32.tf32.tf32.f32 "
        "{%0,%1,%2,%3}, {%4,%5,%6,%7}, {%8,%9}, {%0,%1,%2,%3};\n"
        : "+f"(c[0]), "+f"(c[1]), "+f"(c[2]), "+f"(c[3])
        : "r"(a[0]), "r"(a[1]), "r"(a[2]), "r"(a[3]), "r"(b0), "r"(b1));
}
__device__ __forceinline__ void ldsm_x4(uint32_t r[4], unsigned addr) {
    asm volatile(
        "ldmatrix.sync.aligned.m8n8.x4.shared.b16 {%0,%1,%2,%3}, [%4];\n"
        : "=r"(r[0]), "=r"(r[1]), "=r"(r[2]), "=r"(r[3])
        : "r"(addr));
}

// ---------------------------------------------------------------------------
// Batched elementwise tf32-RN rounding: x, Wq, Wk, Wv in ONE launch.
// ---------------------------------------------------------------------------
__global__ void __launch_bounds__(256)
round4_kernel(const float* __restrict__ x,  float* __restrict__ xr,
              const float* __restrict__ wq, float* __restrict__ wqr,
              const float* __restrict__ wk, float* __restrict__ wkr,
              const float* __restrict__ wv, float* __restrict__ wvr)
{
    int bb = blockIdx.x;
    const float4* src;
    float4* dst;
    if (bb < 8192)       { src = (const float4*)x  + (size_t)bb * 256;
                           dst = (float4*)xr       + (size_t)bb * 256; }
    else if (bb < 12288) { bb -= 8192;
                           src = (const float4*)wq + (size_t)bb * 256;
                           dst = (float4*)wqr      + (size_t)bb * 256; }
    else if (bb < 12544) { bb -= 12288;
                           src = (const float4*)wk + (size_t)bb * 256;
                           dst = (float4*)wkr      + (size_t)bb * 256; }
    else                 { bb -= 12544;
                           src = (const float4*)wv + (size_t)bb * 256;
                           dst = (float4*)wvr      + (size_t)bb * 256; }
    float4 v = src[threadIdx.x];
    v.x = tf32f(v.x); v.y = tf32f(v.y);
    v.z = tf32f(v.z); v.w = tf32f(v.w);
    dst[threadIdx.x] = v;
}

__global__ void __launch_bounds__(256)
round_kernel(const float* __restrict__ in, float* __restrict__ out, int n4)
{
    int i = blockIdx.x * blockDim.x + threadIdx.x;
    if (i < n4) {
        float4 v = ((const float4*)in)[i];
        v.x = tf32f(v.x); v.y = tf32f(v.y);
        v.z = tf32f(v.z); v.w = tf32f(v.w);
        ((float4*)out)[i] = v;
    }
}

// ---------------------------------------------------------------------------
// tf32 tensor-core GEMM (round-6, ldmatrix A-frags).
// TRANSC: store C transposed (C[n][m], ld = MROWS) — used for V^T.
// ---------------------------------------------------------------------------
#define GS 3
#define AS_STRIDE 36
#define BS_STRIDE 136
#define AS_FLOATS (128 * AS_STRIDE)   // 4608
#define BS_FLOATS (32 * BS_STRIDE)    // 4352
#define GEMM_SMEM_BYTES ((GS * (AS_FLOATS + BS_FLOATS)) * 4)  // 107520

template <bool ROUND, bool TRANSC>
__device__ __forceinline__ void gemm_tf32_body(
    const float* __restrict__ A, const float* __restrict__ W,
    float* __restrict__ C, int M, int N, int K,
    int bx, int by)
{
    extern __shared__ float sm[];
    float* As = sm;                      // [GS][128][36]
    float* Bs = sm + GS * AS_FLOATS;     // [GS][32][136]

    const int tid  = threadIdx.x;
    const int warp = tid >> 5, lane = tid & 31;
    const int g    = lane >> 2, tig = lane & 3;
    const int wm   = warp >> 2, wn = warp & 3;
    const int row0 = by * 128, col0 = bx * 128;

    const unsigned lm_off =
        (unsigned)((wm * 64 + (lane & 15)) * AS_STRIDE + 4 * (lane >> 4));

    float acc[4][4][4];
#pragma unroll
    for (int i = 0; i < 4; i++)
#pragma unroll
        for (int j = 0; j < 4; j++)
#pragma unroll
            for (int r = 0; r < 4; r++) acc[i][j][r] = 0.f;

    const int nk = K / 32;

    auto load_stage = [&](int kb, int s) {
        float* as = As + s * AS_FLOATS;
        float* bs = Bs + s * BS_FLOATS;
#pragma unroll
        for (int i = 0; i < 4; i++) {
            int idx = tid + 256 * i;
            int r = idx >> 3, c4 = (idx & 7) * 4;
            cp_async16(smem_u32(&as[r * AS_STRIDE + c4]),
                       &A[(size_t)(row0 + r) * K + kb * 32 + c4]);
        }
#pragma unroll
        for (int i = 0; i < 4; i++) {
            int idx = tid + 256 * i;
            int r = idx >> 5, c4 = (idx & 31) * 4;
            cp_async16(smem_u32(&bs[r * BS_STRIDE + c4]),
                       &W[(size_t)(kb * 32 + r) * N + col0 + c4]);
        }
        asm volatile("cp.async.commit_group;\n");
    };

#pragma unroll
    for (int s = 0; s < GS - 1; s++) load_stage(s, s);

    for (int kb = 0; kb < nk; kb++) {
        asm volatile("cp.async.wait_group %0;\n" :: "n"(GS - 2));
        __syncthreads();
        if (kb + GS - 1 < nk) load_stage(kb + GS - 1, (kb + GS - 1) % GS);

        const float* bs = Bs + (kb % GS) * BS_FLOATS;
        const unsigned as_base =
            smem_u32(As + (kb % GS) * AS_FLOATS) + lm_off * 4u;

#pragma unroll
        for (int ks = 0; ks < 4; ks++) {
            const int kk = ks * 8;
            uint32_t af[4][4], bf[4][2];
#pragma unroll
            for (int i = 0; i < 4; i++)
                ldsm_x4(af[i], as_base + (unsigned)(i * 16 * AS_STRIDE + kk) * 4u);
#pragma unroll
            for (int j = 0; j < 4; j++) {
                int c = wn * 32 + j * 8 + g;
                bf[j][0] = __float_as_uint(bs[(kk + tig) * BS_STRIDE + c]);
                bf[j][1] = __float_as_uint(bs[(kk + tig + 4) * BS_STRIDE + c]);
            }
#pragma unroll
            for (int i = 0; i < 4; i++)
#pragma unroll
                for (int j = 0; j < 4; j++)
                    mma_tf32(acc[i][j], af[i], bf[j][0], bf[j][1]);
        }
    }

#pragma unroll
    for (int i = 0; i < 4; i++) {
        int r = row0 + wm * 64 + i * 16 + g;
#pragma unroll
        for (int j = 0; j < 4; j++) {
            int c = col0 + wn * 32 + j * 8 + 2 * tig;
            float v0 = acc[i][j][0], v1 = acc[i][j][1];
            float v2 = acc[i][j][2], v3 = acc[i][j][3];
            if (ROUND) {
                v0 = tf32f(v0); v1 = tf32f(v1);
                v2 = tf32f(v2); v3 = tf32f(v3);
            }
            if (TRANSC) {
                C[(size_t)c * MROWS + r]           = v0;
                C[(size_t)(c + 1) * MROWS + r]     = v1;
                C[(size_t)c * MROWS + r + 8]       = v2;
                C[(size_t)(c + 1) * MROWS + r + 8] = v3;
            } else {
                *(float2*)&C[(size_t)r * N + c]       = make_float2(v0, v1);
                *(float2*)&C[(size_t)(r + 8) * N + c] = make_float2(v2, v3);
            }
        }
    }
}

// Merged Q/K/V projection: grid.x = 18 (16 Q tiles, 1 K, 1 V-transposed)
__global__ void __launch_bounds__(256, 2)
qkv_gemm_kernel(const float* __restrict__ xr,
                const float* __restrict__ wq, const float* __restrict__ wk,
                const float* __restrict__ wv,
                float* __restrict__ Qo, float* __restrict__ Ko,
                float* __restrict__ VTo)
{
    const int bx = blockIdx.x;
    if (bx < 16) {
        gemm_tf32_body<true, false>(xr, wq, Qo, MROWS, DMODEL, DMODEL,
                                    bx, blockIdx.y);
    } else if (bx == 16) {
        gemm_tf32_body<true, false>(xr, wk, Ko, MROWS, HDIM, DMODEL,
                                    0, blockIdx.y);
    } else {
        gemm_tf32_body<true, true>(xr, wv, VTo, MROWS, HDIM, DMODEL,
                                   0, blockIdx.y);
    }
}

__global__ void __launch_bounds__(256, 2)
o_gemm_kernel(const float* __restrict__ A, const float* __restrict__ W,
              float* __restrict__ C)
{
    gemm_tf32_body<false, false>(A, W, C, MROWS, DMODEL, DMODEL,
                                 blockIdx.x, blockIdx.y);
}

// ---------------------------------------------------------------------------
// Tensor-core flash MQA with ldmatrix on both operands.
// K k-major (rows = keys) -> QK B-frags via ldmatrix.x4 (2 j-tiles per LDSM).
// V stored d-major (V^T) -> PV computed as O^T = V^T(A, ldmatrix) @ P^T(B,
// free from the shuffle transpose of the S C-frags).
// ---------------------------------------------------------------------------
#define BQ   128
#define BKV  64
#define KS_STRIDE  132   // 132*4 % 128 = 16 -> ldmatrix rows conflict-free
#define VST_STRIDE 68    //  68*4 % 128 = 16 -> ldmatrix rows conflict-free
#define KS_FLOATS  (BKV * KS_STRIDE)    // 8448
#define VST_FLOATS (HDIM * VST_STRIDE)  // 8704
#define ATT_SMEM_BYTES ((2 * KS_FLOATS + 2 * VST_FLOATS) * 4)  // 137,216 B

__global__ void __launch_bounds__(256)
mqa_kernel(const float* __restrict__ Qb, const float* __restrict__ Kb,
           const float* __restrict__ VTb, float* __restrict__ Ob)
{
    extern __shared__ float sm[];
    float* KsBuf  = sm;                        // [2][64][132]  keys x dims
    float* VsTBuf = KsBuf + 2 * KS_FLOATS;     // [2][128][68]  dims x keys

    const int tid  = threadIdx.x;
    const int warp = tid >> 5, lane = tid & 31;
    const int g    = lane >> 2, tig = lane & 3;
    const int wm   = warp;
    const int qt   = gridDim.x - 1 - blockIdx.x;   // heavy tiles first
    const int h    = blockIdx.y, b = blockIdx.z;
    const int q0   = qt * BQ;
    const float scale = 0.08838834764831845f;      // 1/sqrt(128)

    // ldmatrix per-lane offsets (element units)
    // K x4: covers j = 2jj, 2jj+1; row = 16jj + 8*jsel + (lane&7), col = kk+4*ksel
    const unsigned lm_k_off =
        (unsigned)(((((lane >> 4) & 1) * 8) + (lane & 7)) * KS_STRIDE
                   + 4 * ((lane >> 3) & 1));
    // V^T x4 (A-frag): row = dt*16 + (lane&15), col = kk + 4*(lane>>4)
    const unsigned lm_v_off =
        (unsigned)((lane & 15) * VST_STRIDE + 4 * (lane >> 4));

    // ---- Q fragments in registers (values already tf32; rescale+reround) ----
    uint32_t qreg[16][4];
    {
        const float* Qg = Qb + ((size_t)(b * SEQ + q0 + wm * 16)) * DMODEL
                             + h * HDIM;
#pragma unroll
        for (int ks = 0; ks < 16; ks++) {
            qreg[ks][0] = tf32u(scale * Qg[(size_t)g * DMODEL + ks * 8 + tig]);
            qreg[ks][1] = tf32u(scale * Qg[(size_t)(g + 8) * DMODEL + ks * 8 + tig]);
            qreg[ks][2] = tf32u(scale * Qg[(size_t)g * DMODEL + ks * 8 + tig + 4]);
            qreg[ks][3] = tf32u(scale * Qg[(size_t)(g + 8) * DMODEL + ks * 8 + tig + 4]);
        }
    }

    // O^T accumulators: ot[dt][qt2] = 16(d) x 8(q) C-frag
    float ot[8][2][4];
#pragma unroll
    for (int dt = 0; dt < 8; dt++)
#pragma unroll
        for (int q2 = 0; q2 < 2; q2++)
#pragma unroll
            for (int r = 0; r < 4; r++) ot[dt][q2][r] = 0.f;

    float m0 = -3.0e38f, m1 = -3.0e38f;   // running max, q rows g / g+8
    float l0 = 0.f, l1 = 0.f;

    const int nkb = 2 * qt + 2;

    auto load_kv = [&](int kb) {
        const int buf = kb & 1;
        const int k0 = kb * BKV;
        const float* Kg = Kb + ((size_t)(b * SEQ + k0)) * HDIM;
        const float* VTg = VTb + (size_t)(b * SEQ + k0);
        float* ks = KsBuf + buf * KS_FLOATS;
        float* vs = VsTBuf + buf * VST_FLOATS;
#pragma unroll
        for (int i = 0; i < 8; i++) {
            int idx = tid + 256 * i;      // 2048 float4 = 64 rows x 32
            int r = idx >> 5, c4 = (idx & 31) * 4;
            cp_async16(smem_u32(&ks[r * KS_STRIDE + c4]),
                       &Kg[(size_t)r * HDIM + c4]);
        }
#pragma unroll
        for (int i = 0; i < 8; i++) {
            int idx = tid + 256 * i;      // 2048 float4 = 128 d-rows x 16
            int r = idx >> 4, c4 = (idx & 15) * 4;
            cp_async16(smem_u32(&vs[r * VST_STRIDE + c4]),
                       &VTg[(size_t)r * MROWS + c4]);
        }
        asm volatile("cp.async.commit_group;\n");
    };

    load_kv(0);

    for (int kb = 0; kb < nkb; kb++) {
        const int k0 = kb * BKV;
        asm volatile("cp.async.wait_group 0;\n");
        __syncthreads();
        if (kb + 1 < nkb) load_kv(kb + 1);

        const unsigned ks_base =
            smem_u32(KsBuf + (kb & 1) * KS_FLOATS) + lm_k_off * 4u;
        const unsigned vs_base =
            smem_u32(VsTBuf + (kb & 1) * VST_FLOATS) + lm_v_off * 4u;

        // ---- S = Q K^T (warp: 16 rows x 64 cols) ----
        float sacc[8][4];
#pragma unroll
        for (int j = 0; j < 8; j++)
#pragma unroll
            for (int r = 0; r < 4; r++) sacc[j][r] = 0.f;

#pragma unroll
        for (int ks4 = 0; ks4 < 16; ks4++) {
            const int kk = ks4 * 8;
            uint32_t kf[4][4];   // kf[jj] = {bf[2jj][0], bf[2jj][1], bf[2jj+1][0], bf[2jj+1][1]}
#pragma unroll
            for (int jj = 0; jj < 4; jj++)
                ldsm_x4(kf[jj],
                        ks_base + (unsigned)(16 * jj * KS_STRIDE + kk) * 4u);
#pragma unroll
            for (int jj = 0; jj < 4; jj++) {
                mma_tf32(sacc[2 * jj],     qreg[ks4], kf[jj][0], kf[jj][1]);
                mma_tf32(sacc[2 * jj + 1], qreg[ks4], kf[jj][2], kf[jj][3]);
            }
        }

        // ---- causal mask ----
        const bool needs_mask = (k0 + BKV - 1 > q0);
        const int rg0 = q0 + wm * 16 + g, rg1 = rg0 + 8;
        if (needs_mask) {
#pragma unroll
            for (int j = 0; j < 8; j++) {
                int cg = k0 + j * 8 + 2 * tig;
                if (cg     > rg0) sacc[j][0] = -3.0e38f;
                if (cg + 1 > rg0) sacc[j][1] = -3.0e38f;
                if (cg     > rg1) sacc[j][2] = -3.0e38f;
                if (cg + 1 > rg1) sacc[j][3] = -3.0e38f;
            }
        }

        // ---- register softmax (quad shfl reductions) ----
        float mx0 = -3.0e38f, mx1 = -3.0e38f;
#pragma unroll
        for (int j = 0; j < 8; j++) {
            mx0 = fmaxf(mx0, fmaxf(sacc[j][0], sacc[j][1]));
            mx1 = fmaxf(mx1, fmaxf(sacc[j][2], sacc[j][3]));
        }
        mx0 = fmaxf(mx0, __shfl_xor_sync(0xffffffffu, mx0, 1));
        mx0 = fmaxf(mx0, __shfl_xor_sync(0xffffffffu, mx0, 2));
        mx1 = fmaxf(mx1, __shfl_xor_sync(0xffffffffu, mx1, 1));
        mx1 = fmaxf(mx1, __shfl_xor_sync(0xffffffffu, mx1, 2));

        float mn0 = fmaxf(m0, mx0), mn1 = fmaxf(m1, mx1);
        float cf0 = __expf(m0 - mn0), cf1 = __expf(m1 - mn1);
        m0 = mn0; m1 = mn1;

        float s0 = 0.f, s1 = 0.f;
#pragma unroll
        for (int j = 0; j < 8; j++) {
            float p0 = tf32f(__expf(sacc[j][0] - mn0));
            float p1 = tf32f(__expf(sacc[j][1] - mn0));
            float p2 = tf32f(__expf(sacc[j][2] - mn1));
            float p3 = tf32f(__expf(sacc[j][3] - mn1));
            sacc[j][0] = p0; sacc[j][1] = p1;
            sacc[j][2] = p2; sacc[j][3] = p3;
            s0 += p0 + p1;
            s1 += p2 + p3;
        }
        s0 += __shfl_xor_sync(0xffffffffu, s0, 1);
        s0 += __shfl_xor_sync(0xffffffffu, s0, 2);
        s1 += __shfl_xor_sync(0xffffffffu, s1, 1);
        s1 += __shfl_xor_sync(0xffffffffu, s1, 2);
        l0 = l0 * cf0 + s0;
        l1 = l1 * cf1 + s1;

        // ---- rescale O^T: per-lane factors for q = 2tig / 2tig+1 ----
        {
            float cfA0 = __shfl_sync(0xffffffffu, cf0, 8 * tig);
            float cfA1 = __shfl_sync(0xffffffffu, cf0, 8 * tig + 4);
            float cfB0 = __shfl_sync(0xffffffffu, cf1, 8 * tig);
            float cfB1 = __shfl_sync(0xffffffffu, cf1, 8 * tig + 4);
#pragma unroll
            for (int dt = 0; dt < 8; dt++) {
                ot[dt][0][0] *= cfA0; ot[dt][0][1] *= cfA1;
                ot[dt][0][2] *= cfA0; ot[dt][0][3] *= cfA1;
                ot[dt][1][0] *= cfB0; ot[dt][1][1] *= cfB1;
                ot[dt][1][2] *= cfB0; ot[dt][1][3] *= cfB1;
            }
        }

        // ---- O^T += V^T @ P^T ----
        const unsigned src1 = (lane & ~3u) | ((unsigned)tig >> 1);
        const unsigned src2 = src1 + 2;
        const bool e = tig & 1;
#pragma unroll
        for (int j = 0; j < 8; j++) {
            // shuffle transpose: P C-frag -> P rows-as-A layout
            float v0 = __shfl_sync(0xffffffffu, sacc[j][0], src1);
            float v1 = __shfl_sync(0xffffffffu, sacc[j][1], src1);
            float v2 = __shfl_sync(0xffffffffu, sacc[j][2], src1);
            float v3 = __shfl_sync(0xffffffffu, sacc[j][3], src1);
            float w0 = __shfl_sync(0xffffffffu, sacc[j][0], src2);
            float w1 = __shfl_sync(0xffffffffu, sacc[j][1], src2);
            float w2 = __shfl_sync(0xffffffffu, sacc[j][2], src2);
            float w3 = __shfl_sync(0xffffffffu, sacc[j][3], src2);
            // B-frags of P^T for the two q-groups:
            uint32_t bq0_0 = __float_as_uint(e ? v1 : v0);  // P[q=g   ][kk+tig]
            uint32_t bq0_1 = __float_as_uint(e ? w1 : w0);  // P[q=g   ][kk+tig+4]
            uint32_t bq1_0 = __float_as_uint(e ? v3 : v2);  // P[q=g+8 ][kk+tig]
            uint32_t bq1_1 = __float_as_uint(e ? w3 : w2);  // P[q=g+8 ][kk+tig+4]

            const int kk = j * 8;
#pragma unroll
            for (int dt = 0; dt < 8; dt++) {
                uint32_t av[4];
                ldsm_x4(av, vs_base +
                        (unsigned)(dt * 16 * VST_STRIDE + kk) * 4u);
                mma_tf32(ot[dt][0], av, bq0_0, bq0_1);
                mma_tf32(ot[dt][1], av, bq1_0, bq1_1);
            }
        }
    }

    // ---- epilogue: normalize, transpose-write O (q-major gmem) ----
    {
        float il0 = 1.f / l0, il1 = 1.f / l1;
        float liA0 = __shfl_sync(0xffffffffu, il0, 8 * tig);
        float liA1 = __shfl_sync(0xffffffffu, il0, 8 * tig + 4);
        float liB0 = __shfl_sync(0xffffffffu, il1, 8 * tig);
        float liB1 = __shfl_sync(0xffffffffu, il1, 8 * tig + 4);
        float* Og = Ob + ((size_t)(b * SEQ + q0 + wm * 16)) * DMODEL + h * HDIM;
#pragma unroll
        for (int q2 = 0; q2 < 2; q2++) {
            float le = q2 ? liB0 : liA0;
            float lo = q2 ? liB1 : liA1;
            size_t r0 = (size_t)(q2 * 8 + 2 * tig) * DMODEL;
            size_t r1 = r0 + DMODEL;
#pragma unroll
            for (int dt = 0; dt < 8; dt++) {
                int d0 = dt * 16 + g;
                Og[r0 + d0]     = tf32f(ot[dt][q2][0] * le);
                Og[r1 + d0]     = tf32f(ot[dt][q2][1] * lo);
                Og[r0 + d0 + 8] = tf32f(ot[dt][q2][2] * le);
                Og[r1 + d0 + 8] = tf32f(ot[dt][q2][3] * lo);
            }
        }
    }
}

// ---------------------------------------------------------------------------
extern "C" void kernel_launch(void* const* d_in, const int* in_sizes, int n_in,
                              void* d_out, int out_size)
{
    (void)in_sizes; (void)n_in; (void)out_size;
    const float* x  = (const float*)d_in[0];
    const float* Wq = (const float*)d_in[1];
    const float* Wk = (const float*)d_in[2];
    const float* Wv = (const float*)d_in[3];
    const float* Wo = (const float*)d_in[4];
    float* out = (float*)d_out;

    float *qp, *kp, *vp, *ap, *wp, *wkp, *wvp;
    cudaGetSymbolAddress((void**)&qp,  g_Q);
    cudaGetSymbolAddress((void**)&kp,  g_K);
    cudaGetSymbolAddress((void**)&vp,  g_V);
    cudaGetSymbolAddress((void**)&ap,  g_A);
    cudaGetSymbolAddress((void**)&wp,  g_W);
    cudaGetSymbolAddress((void**)&wkp, g_Wk);
    cudaGetSymbolAddress((void**)&wvp, g_Wv);

    dim3 blk(256);

    cudaFuncSetAttribute(qkv_gemm_kernel,
                         cudaFuncAttributeMaxDynamicSharedMemorySize,
                         GEMM_SMEM_BYTES);
    cudaFuncSetAttribute(o_gemm_kernel,
                         cudaFuncAttributeMaxDynamicSharedMemorySize,
                         GEMM_SMEM_BYTES);
    cudaFuncSetAttribute(mqa_kernel,
                         cudaFuncAttributeMaxDynamicSharedMemorySize,
                         ATT_SMEM_BYTES);

    // Pre-round x, Wq, Wk, Wv in ONE launch (xr lives in g_A until attention)
    round4_kernel<<<12800, blk>>>(x, ap, Wq, wp, Wk, wkp, Wv, wvp);

    // Fused Q/K/V projection (V written transposed: g_V = V^T [HDIM][MROWS])
    qkv_gemm_kernel<<<dim3(18, MROWS / 128), blk, GEMM_SMEM_BYTES>>>(
        ap, wp, wkp, wvp, qp, kp, vp);

    // Round Wo into the (now free) weight buffer
    round_kernel<<<(DMODEL * DMODEL / 4 + 255) / 256, blk>>>(
        Wo, wp, DMODEL * DMODEL / 4);

    // Flash attention (overwrites g_A with tf32-rounded attention output)
    mqa_kernel<<<dim3(SEQ / BQ, NHEADS, BATCH), blk, ATT_SMEM_BYTES>>>(
        qp, kp, vp, ap);

    // Output projection (fp32 result)
    o_gemm_kernel<<<dim3(DMODEL / 128, MROWS / 128), blk, GEMM_SMEM_BYTES>>>(
        ap, wp, out);
}